// round 7
// baseline (speedup 1.0000x reference)
#include <cuda_runtime.h>
#include <cuda_bf16.h>
#include <cstdint>
#include <cstddef>

#define N_NODES     100000
#define DIM         256
#define N_ET        6
#define M_PER_TYPE  400000
#define TOTAL_EDGES (N_ET * M_PER_TYPE)
#define NBIG        (N_ET * DIM)      /* 1536 */
#define POS_TAB     512
#define SCAN_T      1024
#define SCAN_CHUNK  98               /* 1024*98 = 100352 >= N_NODES */
#define CNT_PAD     (SCAN_T * SCAN_CHUNK)

// ---------------- device scratch (sanctioned: __device__ globals) ----------
__device__ float         g_prop[(size_t)N_NODES * NBIG];   // 614.4 MB
__device__ float         g_gating[POS_TAB * DIM];          // 512 KB
__device__ int           g_cnt[CNT_PAD];
__device__ int           g_off[N_NODES + 1];
__device__ int           g_cur[N_NODES];
__device__ uint32_t      g_sorted[TOTAL_EDGES];            // packed src/type/pos
__device__ __nv_bfloat16 g_Whi[NBIG * DIM];                // W split hi (768 KB)
__device__ __nv_bfloat16 g_Wlo[NBIG * DIM];                // W split lo (768 KB)

// ---------------- W split pre-pass ------------------------------------------
__global__ void convertW_kernel(const float* __restrict__ W) {
    int i = blockIdx.x * blockDim.x + threadIdx.x;
    if (i >= NBIG * DIM) return;
    float x = W[i];
    __nv_bfloat16 h = __float2bfloat16_rn(x);
    g_Whi[i] = h;
    g_Wlo[i] = __float2bfloat16_rn(x - __bfloat162float(h));
}

// ---------------- gating + zero counters ------------------------------------
__global__ void gating_kernel(const float* __restrict__ Wp,
                              const float* __restrict__ bp) {
    __shared__ float emb[DIM];
    const int p = blockIdx.x;
    const int t = threadIdx.x;
    if (t < 127) {
        float y    = (float)(2 * t) / 254.0f;
        float invf = 1.0f / powf(10000.0f, y);
        float ang  = (float)p * invf;
        emb[t]       = sinf(ang);
        emb[t + 127] = cosf(ang);
    } else if (t >= 254) {
        emb[t] = 0.0f;
    }
    int bi = blockIdx.x * blockDim.x + t;
    if (bi < CNT_PAD) g_cnt[bi] = 0;
    __syncthreads();

    float s = bp[t];
    const float* w = Wp + (size_t)t * DIM;
#pragma unroll 8
    for (int k = 0; k < DIM; ++k) s += emb[k] * w[k];
    g_gating[p * DIM + t] = 2.0f / (1.0f + expf(-s));
}

// ---------------- counting sort ---------------------------------------------
__global__ void hist_kernel(const int* __restrict__ edges) {
    int e = blockIdx.x * blockDim.x + threadIdx.x;
    if (e >= TOTAL_EDGES) return;
    atomicAdd(&g_cnt[edges[(size_t)2 * e + 1]], 1);
}

__global__ void scan_kernel() {
    __shared__ int part[SCAN_T];
    int t = threadIdx.x;
    int base = t * SCAN_CHUNK;
    int sum = 0;
#pragma unroll 7
    for (int j = 0; j < SCAN_CHUNK; ++j) {
        int idx = base + j;
        if (idx < N_NODES) sum += g_cnt[idx];
    }
    part[t] = sum;
    __syncthreads();
    for (int off = 1; off < SCAN_T; off <<= 1) {
        int v = (t >= off) ? part[t - off] : 0;
        __syncthreads();
        part[t] += v;
        __syncthreads();
    }
    int run = (t > 0) ? part[t - 1] : 0;
    for (int j = 0; j < SCAN_CHUNK; ++j) {
        int idx = base + j;
        if (idx < N_NODES) {
            g_off[idx] = run;
            g_cur[idx] = run;
            run += g_cnt[idx];
        }
    }
    if (t == SCAN_T - 1) g_off[N_NODES] = part[SCAN_T - 1];
}

__global__ void place_kernel(const int* __restrict__ edges,
                             const int* __restrict__ posl) {
    int e = blockIdx.x * blockDim.x + threadIdx.x;
    if (e >= TOTAL_EDGES) return;
    int src  = edges[(size_t)2 * e];
    int tgt  = edges[(size_t)2 * e + 1];
    int pos  = posl[e];
    int type = e / M_PER_TYPE;
    int p = atomicAdd(&g_cur[tgt], 1);
    g_sorted[p] = ((uint32_t)src << 12) | ((uint32_t)type << 9) | (uint32_t)pos;
}

// ---------------- GEMM: A-resident, loops all 12 N-tiles --------------------
// SMEM layout (dynamic, 168 KB): Ah[128][264], Al[128][264], Bh[128][72], Bl[128][72]
#define A_STRIDE 264
#define B_STRIDE 72
#define OFF_AH   0
#define OFF_AL   (128 * A_STRIDE)              /* halves */
#define OFF_BH   (OFF_AL + 128 * A_STRIDE)
#define OFF_BL   (OFF_BH + 128 * B_STRIDE)
#define SMEM_HALVES (OFF_BL + 128 * B_STRIDE)  /* 86016 halves = 172032 B */

__device__ __forceinline__ void split_pack(float x, float y,
                                           uint32_t& hi, uint32_t& lo) {
    __nv_bfloat16 hx = __float2bfloat16_rn(x);
    __nv_bfloat16 hy = __float2bfloat16_rn(y);
    __nv_bfloat16 lx = __float2bfloat16_rn(x - __bfloat162float(hx));
    __nv_bfloat16 ly = __float2bfloat16_rn(y - __bfloat162float(hy));
    hi = ((uint32_t)__bfloat16_as_ushort(hy) << 16) | __bfloat16_as_ushort(hx);
    lo = ((uint32_t)__bfloat16_as_ushort(ly) << 16) | __bfloat16_as_ushort(lx);
}

__device__ __forceinline__ void mma16(float* d, const uint32_t* a, const uint32_t* b) {
    asm volatile(
        "mma.sync.aligned.m16n8k16.row.col.f32.bf16.bf16.f32 "
        "{%0,%1,%2,%3}, {%4,%5,%6,%7}, {%8,%9}, {%0,%1,%2,%3};"
        : "+f"(d[0]), "+f"(d[1]), "+f"(d[2]), "+f"(d[3])
        : "r"(a[0]), "r"(a[1]), "r"(a[2]), "r"(a[3]), "r"(b[0]), "r"(b[1]));
}

__global__ __launch_bounds__(256, 1)
void gemm_kernel(const float* __restrict__ A, const float* __restrict__ bias) {
    extern __shared__ __nv_bfloat16 sm[];
    __nv_bfloat16* Ah = sm + OFF_AH;
    __nv_bfloat16* Al = sm + OFF_AL;
    __nv_bfloat16* Bh = sm + OFF_BH;
    __nv_bfloat16* Bl = sm + OFF_BL;

    const int tid  = threadIdx.x;
    const int lane = tid & 31;
    const int wid  = tid >> 5;
    const int wm   = (wid & 3) * 32;        // warp M base within 128
    const int wn   = (wid >> 2) * 64;       // warp N base within 128
    const int mBase = blockIdx.x * 128;

    // ---- stage A (128 x 256) once, split to bf16 hi/lo
    for (int i = tid; i < 128 * 64; i += 256) {
        int r = i >> 6, c4 = (i & 63) * 4;
        int gr = mBase + r;
        float4 v = make_float4(0.f, 0.f, 0.f, 0.f);
        if (gr < N_NODES)
            v = *reinterpret_cast<const float4*>(A + (size_t)gr * DIM + c4);
        uint32_t h01, l01, h23, l23;
        split_pack(v.x, v.y, h01, l01);
        split_pack(v.z, v.w, h23, l23);
        __nv_bfloat16* pA = Ah + r * A_STRIDE + c4;
        __nv_bfloat16* pL = Al + r * A_STRIDE + c4;
        *reinterpret_cast<uint32_t*>(pA)     = h01;
        *reinterpret_cast<uint32_t*>(pA + 2) = h23;
        *reinterpret_cast<uint32_t*>(pL)     = l01;
        *reinterpret_cast<uint32_t*>(pL + 2) = l23;
    }

    for (int nt = 0; nt < 12; nt++) {
        const int nBase = nt * 128;
        float acc[2][8][4];
#pragma unroll
        for (int i = 0; i < 2; i++)
#pragma unroll
            for (int j = 0; j < 8; j++)
#pragma unroll
                for (int k = 0; k < 4; k++) acc[i][j][k] = 0.f;

        for (int kc = 0; kc < 4; kc++) {
            __syncthreads();   // prior mma/frag reads of B done before overwrite
            // ---- stage B tile: 128 N-rows x 64 K-cols (bf16 hi/lo, presplit)
            for (int i = tid; i < 128 * 8; i += 256) {
                int r = i >> 3, j8 = (i & 7) * 8;
                size_t gsrc = (size_t)(nBase + r) * DIM + kc * 64 + j8;
                *reinterpret_cast<uint4*>(Bh + r * B_STRIDE + j8) =
                    *reinterpret_cast<const uint4*>(g_Whi + gsrc);
                *reinterpret_cast<uint4*>(Bl + r * B_STRIDE + j8) =
                    *reinterpret_cast<const uint4*>(g_Wlo + gsrc);
            }
            __syncthreads();

#pragma unroll
            for (int s = 0; s < 4; s++) {           // k16 steps
                const int cA = kc * 64 + s * 16 + (lane & 3) * 2;
                const int cB = s * 16 + (lane & 3) * 2;
                uint32_t ah[2][4], al[2][4];
#pragma unroll
                for (int mt = 0; mt < 2; mt++) {
                    const __nv_bfloat16* r0h = Ah + (wm + mt * 16 + (lane >> 2)) * A_STRIDE;
                    const __nv_bfloat16* r0l = Al + (wm + mt * 16 + (lane >> 2)) * A_STRIDE;
                    ah[mt][0] = *reinterpret_cast<const uint32_t*>(r0h + cA);
                    ah[mt][1] = *reinterpret_cast<const uint32_t*>(r0h + 8 * A_STRIDE + cA);
                    ah[mt][2] = *reinterpret_cast<const uint32_t*>(r0h + cA + 8);
                    ah[mt][3] = *reinterpret_cast<const uint32_t*>(r0h + 8 * A_STRIDE + cA + 8);
                    al[mt][0] = *reinterpret_cast<const uint32_t*>(r0l + cA);
                    al[mt][1] = *reinterpret_cast<const uint32_t*>(r0l + 8 * A_STRIDE + cA);
                    al[mt][2] = *reinterpret_cast<const uint32_t*>(r0l + cA + 8);
                    al[mt][3] = *reinterpret_cast<const uint32_t*>(r0l + 8 * A_STRIDE + cA + 8);
                }
#pragma unroll
                for (int ntile = 0; ntile < 8; ntile++) {
                    const __nv_bfloat16* n0h = Bh + (wn + ntile * 8 + (lane >> 2)) * B_STRIDE;
                    const __nv_bfloat16* n0l = Bl + (wn + ntile * 8 + (lane >> 2)) * B_STRIDE;
                    uint32_t bh[2], bl[2];
                    bh[0] = *reinterpret_cast<const uint32_t*>(n0h + cB);
                    bh[1] = *reinterpret_cast<const uint32_t*>(n0h + cB + 8);
                    bl[0] = *reinterpret_cast<const uint32_t*>(n0l + cB);
                    bl[1] = *reinterpret_cast<const uint32_t*>(n0l + cB + 8);
#pragma unroll
                    for (int mt = 0; mt < 2; mt++) {
                        mma16(acc[mt][ntile], ah[mt], bh);  // hi*hi
                        mma16(acc[mt][ntile], ah[mt], bl);  // hi*lo
                        mma16(acc[mt][ntile], al[mt], bh);  // lo*hi
                    }
                }
            }
        }

        // ---- epilogue for this N-tile: +bias, store fp32
#pragma unroll
        for (int mt = 0; mt < 2; mt++) {
#pragma unroll
            for (int ntile = 0; ntile < 8; ntile++) {
                int row = mBase + wm + mt * 16 + (lane >> 2);
                int col = nBase + wn + ntile * 8 + 2 * (lane & 3);
                float b0 = __ldg(bias + col), b1 = __ldg(bias + col + 1);
                if (row < N_NODES) {
                    float2 v = make_float2(acc[mt][ntile][0] + b0, acc[mt][ntile][1] + b1);
                    *reinterpret_cast<float2*>(&g_prop[(size_t)row * NBIG + col]) = v;
                }
                if (row + 8 < N_NODES) {
                    float2 v = make_float2(acc[mt][ntile][2] + b0, acc[mt][ntile][3] + b1);
                    *reinterpret_cast<float2*>(&g_prop[(size_t)(row + 8) * NBIG + col]) = v;
                }
            }
        }
    }
}

// ---------------- message: warp per target, register accumulation ----------
__global__ __launch_bounds__(256)
void message_kernel(float* __restrict__ out) {
    int t    = (blockIdx.x * blockDim.x + threadIdx.x) >> 5;
    int lane = threadIdx.x & 31;
    if (t >= N_NODES) return;

    const int s0 = g_off[t];
    const int s1 = g_off[t + 1];

    float4 a0 = make_float4(0.f, 0.f, 0.f, 0.f);
    float4 a1 = make_float4(0.f, 0.f, 0.f, 0.f);

    uint32_t pk = (s0 < s1) ? g_sorted[s0] : 0u;
    for (int e = s0; e < s1; ++e) {
        uint32_t cur = pk;
        if (e + 1 < s1) pk = g_sorted[e + 1];

        int src  = cur >> 12;
        int type = (cur >> 9) & 7;
        int pos  = cur & 511;

        const float4* __restrict__ p = reinterpret_cast<const float4*>(
            g_prop + (size_t)src * NBIG + type * DIM) + lane * 2;
        const float4* g = reinterpret_cast<const float4*>(
            g_gating + (size_t)pos * DIM) + lane * 2;
        float4 p0 = p[0], p1 = p[1];
        float4 g0 = __ldg(g), g1 = __ldg(g + 1);
        a0.x += p0.x * g0.x; a0.y += p0.y * g0.y;
        a0.z += p0.z * g0.z; a0.w += p0.w * g0.w;
        a1.x += p1.x * g1.x; a1.y += p1.y * g1.y;
        a1.z += p1.z * g1.z; a1.w += p1.w * g1.w;
    }

    int deg = s1 - s0;
    float div = ((deg == 0) ? 1.0f : (float)deg) + 1e-8f;
    float s = 1.0f / div;
    a0.x *= s; a0.y *= s; a0.z *= s; a0.w *= s;
    a1.x *= s; a1.y *= s; a1.z *= s; a1.w *= s;

    float4* dst = reinterpret_cast<float4*>(out + (size_t)t * DIM) + lane * 2;
    dst[0] = a0;
    dst[1] = a1;
}

// ---------------- launch ----------------------------------------------------
extern "C" void kernel_launch(void* const* d_in, const int* in_sizes, int n_in,
                              void* d_out, int out_size) {
    const float* node_states = (const float*)d_in[0];
    const float* W    = (const float*)d_in[1];
    const float* b    = (const float*)d_in[2];
    const float* Wp   = (const float*)d_in[3];
    const float* bp   = (const float*)d_in[4];
    const int*   edges = (const int*)d_in[5];
    const int*   posl  = (const int*)d_in[6];
    float* out = (float*)d_out;

    static int smem_set = 0;
    if (!smem_set) {
        cudaFuncSetAttribute(gemm_kernel,
                             cudaFuncAttributeMaxDynamicSharedMemorySize,
                             SMEM_HALVES * 2);
        smem_set = 1;
    }

    convertW_kernel<<<(NBIG * DIM + 255) / 256, 256>>>(W);
    gating_kernel<<<POS_TAB, 256>>>(Wp, bp);                 // + zero hist
    hist_kernel<<<(TOTAL_EDGES + 255) / 256, 256>>>(edges);
    scan_kernel<<<1, SCAN_T>>>();
    place_kernel<<<(TOTAL_EDGES + 255) / 256, 256>>>(edges, posl);

    gemm_kernel<<<(N_NODES + 127) / 128, 256, SMEM_HALVES * 2>>>(node_states, b);

    message_kernel<<<(N_NODES * 32 + 255) / 256, 256>>>(out);
}

// round 8
// speedup vs baseline: 1.2850x; 1.2850x over previous
#include <cuda_runtime.h>
#include <cuda_bf16.h>
#include <cstdint>
#include <cstddef>

#define N_NODES     100000
#define DIM         256
#define N_ET        6
#define M_PER_TYPE  400000
#define TOTAL_EDGES (N_ET * M_PER_TYPE)
#define NBIG        (N_ET * DIM)      /* 1536 */
#define POS_TAB     512
#define SCAN_BLK    1024
#define N_SBLK      ((N_NODES + SCAN_BLK - 1) / SCAN_BLK)   /* 98 */
#define CNT_PAD     (N_SBLK * SCAN_BLK)

// ---------------- device scratch (sanctioned: __device__ globals) ----------
__device__ float    g_prop[(size_t)N_NODES * NBIG];   // 614.4 MB
__device__ float    g_gating[POS_TAB * DIM];          // 512 KB
__device__ int      g_cnt[CNT_PAD];                   // per-target degree
__device__ int      g_off[N_NODES + 1];               // CSR offsets
__device__ int      g_cur[N_NODES];                   // placement cursors
__device__ int      g_bsum[N_SBLK + 1];               // block sums for scan
__device__ uint32_t g_sorted[TOTAL_EDGES];            // packed src/type/pos

// ---------------- gating + zero counters ------------------------------------
__global__ void gating_kernel(const float* __restrict__ Wp,
                              const float* __restrict__ bp) {
    __shared__ float emb[DIM];
    const int p = blockIdx.x;
    const int t = threadIdx.x;
    if (t < 127) {
        float y    = (float)(2 * t) / 254.0f;
        float invf = 1.0f / powf(10000.0f, y);
        float ang  = (float)p * invf;
        emb[t]       = sinf(ang);
        emb[t + 127] = cosf(ang);
    } else if (t >= 254) {
        emb[t] = 0.0f;
    }
    // piggyback: zero histogram (512*256 = 131072 >= CNT_PAD)
    int bi = blockIdx.x * blockDim.x + t;
    if (bi < CNT_PAD) g_cnt[bi] = 0;
    __syncthreads();

    float s = bp[t];
    const float* w = Wp + (size_t)t * DIM;
#pragma unroll 8
    for (int k = 0; k < DIM; ++k) s += emb[k] * w[k];
    g_gating[p * DIM + t] = 2.0f / (1.0f + expf(-s));
}

// ---------------- counting sort: histogram ----------------------------------
__global__ void hist_kernel(const int* __restrict__ edges) {
    int e = blockIdx.x * blockDim.x + threadIdx.x;
    if (e >= TOTAL_EDGES) return;
    atomicAdd(&g_cnt[edges[(size_t)2 * e + 1]], 1);
}

// ---------------- hierarchical exclusive scan --------------------------------
// phase 1: per-block exclusive scan of 1024 counters; emit block total
__global__ void scan1_kernel() {
    __shared__ int sh[SCAN_BLK];
    int t   = threadIdx.x;
    int idx = blockIdx.x * SCAN_BLK + t;
    int v   = (idx < N_NODES) ? g_cnt[idx] : 0;
    sh[t] = v;
    __syncthreads();
#pragma unroll
    for (int off = 1; off < SCAN_BLK; off <<= 1) {
        int x = (t >= off) ? sh[t - off] : 0;
        __syncthreads();
        sh[t] += x;
        __syncthreads();
    }
    if (idx < N_NODES) g_off[idx] = sh[t] - v;     // exclusive within block
    if (t == SCAN_BLK - 1) g_bsum[blockIdx.x] = sh[t];
}

// phase 2: scan the 98 block sums (single tiny block)
__global__ void scan2_kernel() {
    __shared__ int sh[128];
    int t = threadIdx.x;
    int v = (t < N_SBLK) ? g_bsum[t] : 0;
    sh[t] = v;
    __syncthreads();
#pragma unroll
    for (int off = 1; off < 128; off <<= 1) {
        int x = (t >= off) ? sh[t - off] : 0;
        __syncthreads();
        sh[t] += x;
        __syncthreads();
    }
    if (t < N_SBLK) g_bsum[t] = sh[t] - v;         // exclusive block offsets
    if (t == 127) g_off[N_NODES] = sh[127];        // grand total
}

// phase 3: add block offsets, init cursors
__global__ void scan3_kernel() {
    int idx = blockIdx.x * SCAN_BLK + threadIdx.x;
    if (idx >= N_NODES) return;
    int o = g_off[idx] + g_bsum[blockIdx.x];
    g_off[idx] = o;
    g_cur[idx] = o;
}

// ---------------- counting sort: placement ----------------------------------
__global__ void place_kernel(const int* __restrict__ edges,
                             const int* __restrict__ posl) {
    int e = blockIdx.x * blockDim.x + threadIdx.x;
    if (e >= TOTAL_EDGES) return;
    int src  = edges[(size_t)2 * e];
    int tgt  = edges[(size_t)2 * e + 1];
    int pos  = posl[e];
    int type = e / M_PER_TYPE;
    int p = atomicAdd(&g_cur[tgt], 1);
    g_sorted[p] = ((uint32_t)src << 12) | ((uint32_t)type << 9) | (uint32_t)pos;
}

// ---------------- GEMM: prop = node_states @ W^T + b (3x bf16 mma) ---------
__device__ __forceinline__ void split_pack(float x, float y,
                                           uint32_t& hi, uint32_t& lo) {
    __nv_bfloat16 hx = __float2bfloat16_rn(x);
    __nv_bfloat16 hy = __float2bfloat16_rn(y);
    __nv_bfloat16 lx = __float2bfloat16_rn(x - __bfloat162float(hx));
    __nv_bfloat16 ly = __float2bfloat16_rn(y - __bfloat162float(hy));
    hi = ((uint32_t)__bfloat16_as_ushort(hy) << 16) | __bfloat16_as_ushort(hx);
    lo = ((uint32_t)__bfloat16_as_ushort(ly) << 16) | __bfloat16_as_ushort(lx);
}

__device__ __forceinline__ void mma16(float* d, const uint32_t* a, const uint32_t* b) {
    asm volatile(
        "mma.sync.aligned.m16n8k16.row.col.f32.bf16.bf16.f32 "
        "{%0,%1,%2,%3}, {%4,%5,%6,%7}, {%8,%9}, {%0,%1,%2,%3};"
        : "+f"(d[0]), "+f"(d[1]), "+f"(d[2]), "+f"(d[3])
        : "r"(a[0]), "r"(a[1]), "r"(a[2]), "r"(a[3]), "r"(b[0]), "r"(b[1]));
}

__global__ __launch_bounds__(256, 2)
void gemm_kernel(const float* __restrict__ A, const float* __restrict__ W,
                 const float* __restrict__ bias) {
    __shared__ __nv_bfloat16 Ah[128][40], Al[128][40];
    __shared__ __nv_bfloat16 Bh[64][40],  Bl[64][40];
    const int tid  = threadIdx.x;
    const int lane = tid & 31;
    const int wid  = tid >> 5;
    const int wm   = (wid & 3) * 32;
    const int wn   = (wid >> 2) * 32;
    const int mBase = blockIdx.y * 128;
    const int nBase = blockIdx.x * 64;

    float acc[2][4][4];
#pragma unroll
    for (int i = 0; i < 2; i++)
#pragma unroll
        for (int j = 0; j < 4; j++)
#pragma unroll
            for (int k = 0; k < 4; k++) acc[i][j][k] = 0.f;

    for (int k0 = 0; k0 < DIM; k0 += 32) {
#pragma unroll
        for (int i = tid; i < 128 * 8; i += 256) {
            int r = i >> 3, c4 = (i & 7) * 4;
            int gr = mBase + r;
            float4 v = make_float4(0.f, 0.f, 0.f, 0.f);
            if (gr < N_NODES)
                v = *reinterpret_cast<const float4*>(A + (size_t)gr * DIM + k0 + c4);
            uint32_t h01, l01, h23, l23;
            split_pack(v.x, v.y, h01, l01);
            split_pack(v.z, v.w, h23, l23);
            *reinterpret_cast<uint32_t*>(&Ah[r][c4])     = h01;
            *reinterpret_cast<uint32_t*>(&Ah[r][c4 + 2]) = h23;
            *reinterpret_cast<uint32_t*>(&Al[r][c4])     = l01;
            *reinterpret_cast<uint32_t*>(&Al[r][c4 + 2]) = l23;
        }
#pragma unroll
        for (int i = tid; i < 64 * 8; i += 256) {
            int r = i >> 3, c4 = (i & 7) * 4;
            float4 v = *reinterpret_cast<const float4*>(
                W + (size_t)(nBase + r) * DIM + k0 + c4);
            uint32_t h01, l01, h23, l23;
            split_pack(v.x, v.y, h01, l01);
            split_pack(v.z, v.w, h23, l23);
            *reinterpret_cast<uint32_t*>(&Bh[r][c4])     = h01;
            *reinterpret_cast<uint32_t*>(&Bh[r][c4 + 2]) = h23;
            *reinterpret_cast<uint32_t*>(&Bl[r][c4])     = l01;
            *reinterpret_cast<uint32_t*>(&Bl[r][c4 + 2]) = l23;
        }
        __syncthreads();

#pragma unroll
        for (int kk = 0; kk < 32; kk += 16) {
            const int cA = kk + (lane & 3) * 2;
            uint32_t ah[2][4], al[2][4];
#pragma unroll
            for (int mt = 0; mt < 2; mt++) {
                int r0 = wm + mt * 16 + (lane >> 2);
                ah[mt][0] = *reinterpret_cast<const uint32_t*>(&Ah[r0][cA]);
                ah[mt][1] = *reinterpret_cast<const uint32_t*>(&Ah[r0 + 8][cA]);
                ah[mt][2] = *reinterpret_cast<const uint32_t*>(&Ah[r0][cA + 8]);
                ah[mt][3] = *reinterpret_cast<const uint32_t*>(&Ah[r0 + 8][cA + 8]);
                al[mt][0] = *reinterpret_cast<const uint32_t*>(&Al[r0][cA]);
                al[mt][1] = *reinterpret_cast<const uint32_t*>(&Al[r0 + 8][cA]);
                al[mt][2] = *reinterpret_cast<const uint32_t*>(&Al[r0][cA + 8]);
                al[mt][3] = *reinterpret_cast<const uint32_t*>(&Al[r0 + 8][cA + 8]);
            }
            uint32_t bh[4][2], bl[4][2];
#pragma unroll
            for (int nt = 0; nt < 4; nt++) {
                int n0 = wn + nt * 8 + (lane >> 2);
                bh[nt][0] = *reinterpret_cast<const uint32_t*>(&Bh[n0][cA]);
                bh[nt][1] = *reinterpret_cast<const uint32_t*>(&Bh[n0][cA + 8]);
                bl[nt][0] = *reinterpret_cast<const uint32_t*>(&Bl[n0][cA]);
                bl[nt][1] = *reinterpret_cast<const uint32_t*>(&Bl[n0][cA + 8]);
            }
#pragma unroll
            for (int mt = 0; mt < 2; mt++)
#pragma unroll
                for (int nt = 0; nt < 4; nt++) {
                    mma16(acc[mt][nt], ah[mt], bh[nt]);
                    mma16(acc[mt][nt], ah[mt], bl[nt]);
                    mma16(acc[mt][nt], al[mt], bh[nt]);
                }
        }
        __syncthreads();
    }

#pragma unroll
    for (int mt = 0; mt < 2; mt++) {
#pragma unroll
        for (int nt = 0; nt < 4; nt++) {
            int row = mBase + wm + mt * 16 + (lane >> 2);
            int col = nBase + wn + nt * 8 + 2 * (lane & 3);
            float b0 = bias[col], b1 = bias[col + 1];
            if (row < N_NODES) {
                float2 v = make_float2(acc[mt][nt][0] + b0, acc[mt][nt][1] + b1);
                *reinterpret_cast<float2*>(&g_prop[(size_t)row * NBIG + col]) = v;
            }
            if (row + 8 < N_NODES) {
                float2 v = make_float2(acc[mt][nt][2] + b0, acc[mt][nt][3] + b1);
                *reinterpret_cast<float2*>(&g_prop[(size_t)(row + 8) * NBIG + col]) = v;
            }
        }
    }
}

// ---------------- message: warp per target, register accumulation ----------
__global__ __launch_bounds__(256)
void message_kernel(float* __restrict__ out) {
    int t    = (blockIdx.x * blockDim.x + threadIdx.x) >> 5;
    int lane = threadIdx.x & 31;
    if (t >= N_NODES) return;

    const int s0 = g_off[t];
    const int s1 = g_off[t + 1];

    float4 a0 = make_float4(0.f, 0.f, 0.f, 0.f);
    float4 a1 = make_float4(0.f, 0.f, 0.f, 0.f);

    uint32_t pk = (s0 < s1) ? g_sorted[s0] : 0u;
    for (int e = s0; e < s1; ++e) {
        uint32_t cur = pk;
        if (e + 1 < s1) pk = g_sorted[e + 1];

        int src  = cur >> 12;
        int type = (cur >> 9) & 7;
        int pos  = cur & 511;

        const float4* __restrict__ p = reinterpret_cast<const float4*>(
            g_prop + (size_t)src * NBIG + type * DIM) + lane * 2;
        const float4* g = reinterpret_cast<const float4*>(
            g_gating + (size_t)pos * DIM) + lane * 2;
        float4 p0 = p[0], p1 = p[1];
        float4 g0 = __ldg(g), g1 = __ldg(g + 1);
        a0.x += p0.x * g0.x; a0.y += p0.y * g0.y;
        a0.z += p0.z * g0.z; a0.w += p0.w * g0.w;
        a1.x += p1.x * g1.x; a1.y += p1.y * g1.y;
        a1.z += p1.z * g1.z; a1.w += p1.w * g1.w;
    }

    int deg = s1 - s0;
    float div = ((deg == 0) ? 1.0f : (float)deg) + 1e-8f;
    float s = 1.0f / div;
    a0.x *= s; a0.y *= s; a0.z *= s; a0.w *= s;
    a1.x *= s; a1.y *= s; a1.z *= s; a1.w *= s;

    float4* dst = reinterpret_cast<float4*>(out + (size_t)t * DIM) + lane * 2;
    dst[0] = a0;
    dst[1] = a1;
}

// ---------------- launch ----------------------------------------------------
extern "C" void kernel_launch(void* const* d_in, const int* in_sizes, int n_in,
                              void* d_out, int out_size) {
    const float* node_states = (const float*)d_in[0];
    const float* W    = (const float*)d_in[1];
    const float* b    = (const float*)d_in[2];
    const float* Wp   = (const float*)d_in[3];
    const float* bp   = (const float*)d_in[4];
    const int*   edges = (const int*)d_in[5];
    const int*   posl  = (const int*)d_in[6];
    float* out = (float*)d_out;

    gating_kernel<<<POS_TAB, 256>>>(Wp, bp);                 // + zero hist
    hist_kernel<<<(TOTAL_EDGES + 255) / 256, 256>>>(edges);
    scan1_kernel<<<N_SBLK, SCAN_BLK>>>();
    scan2_kernel<<<1, 128>>>();
    scan3_kernel<<<N_SBLK, SCAN_BLK>>>();
    place_kernel<<<(TOTAL_EDGES + 255) / 256, 256>>>(edges, posl);

    dim3 gg(NBIG / 64, (N_NODES + 127) / 128);
    gemm_kernel<<<gg, 256>>>(node_states, W, b);

    message_kernel<<<(N_NODES * 32 + 255) / 256, 256>>>(out);
}

// round 10
// speedup vs baseline: 1.3972x; 1.0872x over previous
#include <cuda_runtime.h>
#include <cuda_bf16.h>
#include <cuda_fp16.h>
#include <cstdint>
#include <cstddef>

#define N_NODES     100000
#define DIM         256
#define N_ET        6
#define M_PER_TYPE  400000
#define TOTAL_EDGES (N_ET * M_PER_TYPE)
#define NBIG        (N_ET * DIM)      /* 1536 */
#define POS_TAB     512
#define SCAN_BLK    1024
#define N_SBLK      ((N_NODES + SCAN_BLK - 1) / SCAN_BLK)   /* 98 */
#define CNT_PAD     (N_SBLK * SCAN_BLK)

// ---------------- device scratch (sanctioned: __device__ globals) ----------
__device__ __half   g_proph[(size_t)N_NODES * NBIG];  // 307.2 MB (fp16 prop)
__device__ float    g_gating[POS_TAB * DIM];          // 512 KB
__device__ int      g_cnt[CNT_PAD];
__device__ int      g_off[N_NODES + 1];
__device__ int      g_cur[N_NODES];
__device__ int      g_bsum[N_SBLK + 1];
__device__ uint32_t g_sorted[TOTAL_EDGES];            // packed src/type/pos

// ---------------- gating + zero counters ------------------------------------
__global__ void gating_kernel(const float* __restrict__ Wp,
                              const float* __restrict__ bp) {
    __shared__ float emb[DIM];
    const int p = blockIdx.x;
    const int t = threadIdx.x;
    if (t < 127) {
        float y    = (float)(2 * t) / 254.0f;
        float invf = 1.0f / powf(10000.0f, y);
        float ang  = (float)p * invf;
        emb[t]       = sinf(ang);
        emb[t + 127] = cosf(ang);
    } else if (t >= 254) {
        emb[t] = 0.0f;
    }
    int bi = blockIdx.x * blockDim.x + t;
    if (bi < CNT_PAD) g_cnt[bi] = 0;
    __syncthreads();

    float s = bp[t];
    const float* w = Wp + (size_t)t * DIM;
#pragma unroll 8
    for (int k = 0; k < DIM; ++k) s += emb[k] * w[k];
    g_gating[p * DIM + t] = 2.0f / (1.0f + expf(-s));
}

// ---------------- counting sort: histogram ----------------------------------
__global__ void hist_kernel(const int* __restrict__ edges) {
    int e = blockIdx.x * blockDim.x + threadIdx.x;
    if (e >= TOTAL_EDGES) return;
    atomicAdd(&g_cnt[edges[(size_t)2 * e + 1]], 1);
}

// ---------------- hierarchical exclusive scan --------------------------------
__global__ void scan1_kernel() {
    __shared__ int sh[SCAN_BLK];
    int t   = threadIdx.x;
    int idx = blockIdx.x * SCAN_BLK + t;
    int v   = (idx < N_NODES) ? g_cnt[idx] : 0;
    sh[t] = v;
    __syncthreads();
#pragma unroll
    for (int off = 1; off < SCAN_BLK; off <<= 1) {
        int x = (t >= off) ? sh[t - off] : 0;
        __syncthreads();
        sh[t] += x;
        __syncthreads();
    }
    if (idx < N_NODES) g_off[idx] = sh[t] - v;
    if (t == SCAN_BLK - 1) g_bsum[blockIdx.x] = sh[t];
}

__global__ void scan2_kernel() {
    __shared__ int sh[128];
    int t = threadIdx.x;
    int v = (t < N_SBLK) ? g_bsum[t] : 0;
    sh[t] = v;
    __syncthreads();
#pragma unroll
    for (int off = 1; off < 128; off <<= 1) {
        int x = (t >= off) ? sh[t - off] : 0;
        __syncthreads();
        sh[t] += x;
        __syncthreads();
    }
    if (t < N_SBLK) g_bsum[t] = sh[t] - v;
    if (t == 127) g_off[N_NODES] = sh[127];
}

__global__ void scan3_kernel() {
    int idx = blockIdx.x * SCAN_BLK + threadIdx.x;
    if (idx >= N_NODES) return;
    int o = g_off[idx] + g_bsum[blockIdx.x];
    g_off[idx] = o;
    g_cur[idx] = o;
}

// ---------------- counting sort: placement ----------------------------------
__global__ void place_kernel(const int* __restrict__ edges,
                             const int* __restrict__ posl) {
    int e = blockIdx.x * blockDim.x + threadIdx.x;
    if (e >= TOTAL_EDGES) return;
    int src  = edges[(size_t)2 * e];
    int tgt  = edges[(size_t)2 * e + 1];
    int pos  = posl[e];
    int type = e / M_PER_TYPE;
    int p = atomicAdd(&g_cur[tgt], 1);
    g_sorted[p] = ((uint32_t)src << 12) | ((uint32_t)type << 9) | (uint32_t)pos;
}

// ---------------- GEMM: prop = node_states @ W^T + b (3x bf16 mma) ---------
__device__ __forceinline__ void split_pack(float x, float y,
                                           uint32_t& hi, uint32_t& lo) {
    __nv_bfloat16 hx = __float2bfloat16_rn(x);
    __nv_bfloat16 hy = __float2bfloat16_rn(y);
    __nv_bfloat16 lx = __float2bfloat16_rn(x - __bfloat162float(hx));
    __nv_bfloat16 ly = __float2bfloat16_rn(y - __bfloat162float(hy));
    hi = ((uint32_t)__bfloat16_as_ushort(hy) << 16) | __bfloat16_as_ushort(hx);
    lo = ((uint32_t)__bfloat16_as_ushort(ly) << 16) | __bfloat16_as_ushort(lx);
}

__device__ __forceinline__ void mma16(float* d, const uint32_t* a, const uint32_t* b) {
    asm volatile(
        "mma.sync.aligned.m16n8k16.row.col.f32.bf16.bf16.f32 "
        "{%0,%1,%2,%3}, {%4,%5,%6,%7}, {%8,%9}, {%0,%1,%2,%3};"
        : "+f"(d[0]), "+f"(d[1]), "+f"(d[2]), "+f"(d[3])
        : "r"(a[0]), "r"(a[1]), "r"(a[2]), "r"(a[3]), "r"(b[0]), "r"(b[1]));
}

__global__ __launch_bounds__(256, 2)
void gemm_kernel(const float* __restrict__ A, const float* __restrict__ W,
                 const float* __restrict__ bias) {
    __shared__ __nv_bfloat16 Ah[128][40], Al[128][40];
    __shared__ __nv_bfloat16 Bh[64][40],  Bl[64][40];
    const int tid  = threadIdx.x;
    const int lane = tid & 31;
    const int wid  = tid >> 5;
    const int wm   = (wid & 3) * 32;
    const int wn   = (wid >> 2) * 32;
    const int mBase = blockIdx.y * 128;
    const int nBase = blockIdx.x * 64;

    float acc[2][4][4];
#pragma unroll
    for (int i = 0; i < 2; i++)
#pragma unroll
        for (int j = 0; j < 4; j++)
#pragma unroll
            for (int k = 0; k < 4; k++) acc[i][j][k] = 0.f;

    for (int k0 = 0; k0 < DIM; k0 += 32) {
#pragma unroll
        for (int i = tid; i < 128 * 8; i += 256) {
            int r = i >> 3, c4 = (i & 7) * 4;
            int gr = mBase + r;
            float4 v = make_float4(0.f, 0.f, 0.f, 0.f);
            if (gr < N_NODES)
                v = *reinterpret_cast<const float4*>(A + (size_t)gr * DIM + k0 + c4);
            uint32_t h01, l01, h23, l23;
            split_pack(v.x, v.y, h01, l01);
            split_pack(v.z, v.w, h23, l23);
            *reinterpret_cast<uint32_t*>(&Ah[r][c4])     = h01;
            *reinterpret_cast<uint32_t*>(&Ah[r][c4 + 2]) = h23;
            *reinterpret_cast<uint32_t*>(&Al[r][c4])     = l01;
            *reinterpret_cast<uint32_t*>(&Al[r][c4 + 2]) = l23;
        }
#pragma unroll
        for (int i = tid; i < 64 * 8; i += 256) {
            int r = i >> 3, c4 = (i & 7) * 4;
            float4 v = *reinterpret_cast<const float4*>(
                W + (size_t)(nBase + r) * DIM + k0 + c4);
            uint32_t h01, l01, h23, l23;
            split_pack(v.x, v.y, h01, l01);
            split_pack(v.z, v.w, h23, l23);
            *reinterpret_cast<uint32_t*>(&Bh[r][c4])     = h01;
            *reinterpret_cast<uint32_t*>(&Bh[r][c4 + 2]) = h23;
            *reinterpret_cast<uint32_t*>(&Bl[r][c4])     = l01;
            *reinterpret_cast<uint32_t*>(&Bl[r][c4 + 2]) = l23;
        }
        __syncthreads();

#pragma unroll
        for (int kk = 0; kk < 32; kk += 16) {
            const int cA = kk + (lane & 3) * 2;
            uint32_t ah[2][4], al[2][4];
#pragma unroll
            for (int mt = 0; mt < 2; mt++) {
                int r0 = wm + mt * 16 + (lane >> 2);
                ah[mt][0] = *reinterpret_cast<const uint32_t*>(&Ah[r0][cA]);
                ah[mt][1] = *reinterpret_cast<const uint32_t*>(&Ah[r0 + 8][cA]);
                ah[mt][2] = *reinterpret_cast<const uint32_t*>(&Ah[r0][cA + 8]);
                ah[mt][3] = *reinterpret_cast<const uint32_t*>(&Ah[r0 + 8][cA + 8]);
                al[mt][0] = *reinterpret_cast<const uint32_t*>(&Al[r0][cA]);
                al[mt][1] = *reinterpret_cast<const uint32_t*>(&Al[r0 + 8][cA]);
                al[mt][2] = *reinterpret_cast<const uint32_t*>(&Al[r0][cA + 8]);
                al[mt][3] = *reinterpret_cast<const uint32_t*>(&Al[r0 + 8][cA + 8]);
            }
            uint32_t bh[4][2], bl[4][2];
#pragma unroll
            for (int nt = 0; nt < 4; nt++) {
                int n0 = wn + nt * 8 + (lane >> 2);
                bh[nt][0] = *reinterpret_cast<const uint32_t*>(&Bh[n0][cA]);
                bh[nt][1] = *reinterpret_cast<const uint32_t*>(&Bh[n0][cA + 8]);
                bl[nt][0] = *reinterpret_cast<const uint32_t*>(&Bl[n0][cA]);
                bl[nt][1] = *reinterpret_cast<const uint32_t*>(&Bl[n0][cA + 8]);
            }
#pragma unroll
            for (int mt = 0; mt < 2; mt++)
#pragma unroll
                for (int nt = 0; nt < 4; nt++) {
                    mma16(acc[mt][nt], ah[mt], bh[nt]);
                    mma16(acc[mt][nt], ah[mt], bl[nt]);
                    mma16(acc[mt][nt], al[mt], bh[nt]);
                }
        }
        __syncthreads();
    }

    // ---- epilogue: +bias, store fp16
#pragma unroll
    for (int mt = 0; mt < 2; mt++) {
#pragma unroll
        for (int nt = 0; nt < 4; nt++) {
            int row = mBase + wm + mt * 16 + (lane >> 2);
            int col = nBase + wn + nt * 8 + 2 * (lane & 3);
            float b0 = bias[col], b1 = bias[col + 1];
            if (row < N_NODES) {
                __half2 h = __floats2half2_rn(acc[mt][nt][0] + b0, acc[mt][nt][1] + b1);
                *reinterpret_cast<__half2*>(&g_proph[(size_t)row * NBIG + col]) = h;
            }
            if (row + 8 < N_NODES) {
                __half2 h = __floats2half2_rn(acc[mt][nt][2] + b0, acc[mt][nt][3] + b1);
                *reinterpret_cast<__half2*>(&g_proph[(size_t)(row + 8) * NBIG + col]) = h;
            }
        }
    }
}

// ---------------- message: warp per target, fp16 gather ---------------------
__global__ __launch_bounds__(256)
void message_kernel(float* __restrict__ out) {
    int t    = (blockIdx.x * blockDim.x + threadIdx.x) >> 5;
    int lane = threadIdx.x & 31;
    if (t >= N_NODES) return;

    const int s0 = g_off[t];
    const int s1 = g_off[t + 1];

    float4 a0 = make_float4(0.f, 0.f, 0.f, 0.f);
    float4 a1 = make_float4(0.f, 0.f, 0.f, 0.f);

    uint32_t pk = (s0 < s1) ? g_sorted[s0] : 0u;
    for (int e = s0; e < s1; ++e) {
        uint32_t cur = pk;
        if (e + 1 < s1) pk = g_sorted[e + 1];

        int src  = cur >> 12;
        int type = (cur >> 9) & 7;
        int pos  = cur & 511;

        // 8 halves per lane = one uint4 (512 B per row, fully coalesced)
        const uint4* __restrict__ p = reinterpret_cast<const uint4*>(
            g_proph + (size_t)src * NBIG + type * DIM) + lane;
        uint4 pv = __ldg(p);
        float2 f0 = __half22float2(*reinterpret_cast<__half2*>(&pv.x));
        float2 f1 = __half22float2(*reinterpret_cast<__half2*>(&pv.y));
        float2 f2 = __half22float2(*reinterpret_cast<__half2*>(&pv.z));
        float2 f3 = __half22float2(*reinterpret_cast<__half2*>(&pv.w));

        const float4* g = reinterpret_cast<const float4*>(
            g_gating + (size_t)pos * DIM) + lane * 2;
        float4 g0 = __ldg(g), g1 = __ldg(g + 1);

        a0.x += f0.x * g0.x; a0.y += f0.y * g0.y;
        a0.z += f1.x * g0.z; a0.w += f1.y * g0.w;
        a1.x += f2.x * g1.x; a1.y += f2.y * g1.y;
        a1.z += f3.x * g1.z; a1.w += f3.y * g1.w;
    }

    int deg = s1 - s0;
    float div = ((deg == 0) ? 1.0f : (float)deg) + 1e-8f;
    float s = 1.0f / div;
    a0.x *= s; a0.y *= s; a0.z *= s; a0.w *= s;
    a1.x *= s; a1.y *= s; a1.z *= s; a1.w *= s;

    float4* dst = reinterpret_cast<float4*>(out + (size_t)t * DIM) + lane * 2;
    dst[0] = a0;
    dst[1] = a1;
}

// ---------------- launch ----------------------------------------------------
extern "C" void kernel_launch(void* const* d_in, const int* in_sizes, int n_in,
                              void* d_out, int out_size) {
    const float* node_states = (const float*)d_in[0];
    const float* W    = (const float*)d_in[1];
    const float* b    = (const float*)d_in[2];
    const float* Wp   = (const float*)d_in[3];
    const float* bp   = (const float*)d_in[4];
    const int*   edges = (const int*)d_in[5];
    const int*   posl  = (const int*)d_in[6];
    float* out = (float*)d_out;

    gating_kernel<<<POS_TAB, 256>>>(Wp, bp);                 // + zero hist
    hist_kernel<<<(TOTAL_EDGES + 255) / 256, 256>>>(edges);
    scan1_kernel<<<N_SBLK, SCAN_BLK>>>();
    scan2_kernel<<<1, 128>>>();
    scan3_kernel<<<N_SBLK, SCAN_BLK>>>();
    place_kernel<<<(TOTAL_EDGES + 255) / 256, 256>>>(edges, posl);

    dim3 gg(NBIG / 64, (N_NODES + 127) / 128);
    gemm_kernel<<<gg, 256>>>(node_states, W, b);

    message_kernel<<<(N_NODES * 32 + 255) / 256, 256>>>(out);
}

// round 11
// speedup vs baseline: 1.4308x; 1.0241x over previous
#include <cuda_runtime.h>
#include <cuda_bf16.h>
#include <cuda_fp16.h>
#include <cstdint>
#include <cstddef>

#define N_NODES     100000
#define N_PAD       100096            /* 782 * 128 */
#define DIM         256
#define N_ET        6
#define M_PER_TYPE  400000
#define TOTAL_EDGES (N_ET * M_PER_TYPE)
#define NBIG        (N_ET * DIM)      /* 1536 */
#define POS_TAB     512
#define SCAN_BLK    1024
#define N_SBLK      ((N_NODES + SCAN_BLK - 1) / SCAN_BLK)   /* 98 */
#define CNT_PAD     (N_SBLK * SCAN_BLK)

// ---------------- device scratch (sanctioned: __device__ globals) ----------
__device__ __half         g_proph[(size_t)N_NODES * NBIG]; // 307.2 MB
__device__ float          g_gating[POS_TAB * DIM];
__device__ int            g_cnt[CNT_PAD];
__device__ int            g_off[N_NODES + 1];
__device__ int            g_cur[N_NODES];
__device__ int            g_bsum[N_SBLK + 1];
__device__ uint32_t       g_sorted[TOTAL_EDGES];
__device__ __nv_bfloat16  g_Ahi[(size_t)N_PAD * DIM];      // 51.2 MB (pad rows stay 0)
__device__ __nv_bfloat16  g_Alo[(size_t)N_PAD * DIM];
__device__ __nv_bfloat16  g_Whi[NBIG * DIM];
__device__ __nv_bfloat16  g_Wlo[NBIG * DIM];

// ---------------- pre-split passes ------------------------------------------
__global__ void convertA_kernel(const float* __restrict__ A) {
    int i = blockIdx.x * blockDim.x + threadIdx.x;
    if (i >= N_NODES * DIM) return;
    float x = A[i];
    __nv_bfloat16 h = __float2bfloat16_rn(x);
    g_Ahi[i] = h;
    g_Alo[i] = __float2bfloat16_rn(x - __bfloat162float(h));
}
__global__ void convertW_kernel(const float* __restrict__ W) {
    int i = blockIdx.x * blockDim.x + threadIdx.x;
    if (i >= NBIG * DIM) return;
    float x = W[i];
    __nv_bfloat16 h = __float2bfloat16_rn(x);
    g_Whi[i] = h;
    g_Wlo[i] = __float2bfloat16_rn(x - __bfloat162float(h));
}

// ---------------- gating + zero counters ------------------------------------
__global__ void gating_kernel(const float* __restrict__ Wp,
                              const float* __restrict__ bp) {
    __shared__ float emb[DIM];
    const int p = blockIdx.x;
    const int t = threadIdx.x;
    if (t < 127) {
        float y    = (float)(2 * t) / 254.0f;
        float invf = 1.0f / powf(10000.0f, y);
        float ang  = (float)p * invf;
        emb[t]       = sinf(ang);
        emb[t + 127] = cosf(ang);
    } else if (t >= 254) {
        emb[t] = 0.0f;
    }
    int bi = blockIdx.x * blockDim.x + t;
    if (bi < CNT_PAD) g_cnt[bi] = 0;
    __syncthreads();

    float s = bp[t];
    const float* w = Wp + (size_t)t * DIM;
#pragma unroll 8
    for (int k = 0; k < DIM; ++k) s += emb[k] * w[k];
    g_gating[p * DIM + t] = 2.0f / (1.0f + expf(-s));
}

// ---------------- counting sort ---------------------------------------------
__global__ void hist_kernel(const int* __restrict__ edges) {
    int e = blockIdx.x * blockDim.x + threadIdx.x;
    if (e >= TOTAL_EDGES) return;
    atomicAdd(&g_cnt[edges[(size_t)2 * e + 1]], 1);
}

__global__ void scan1_kernel() {
    __shared__ int sh[SCAN_BLK];
    int t   = threadIdx.x;
    int idx = blockIdx.x * SCAN_BLK + t;
    int v   = (idx < N_NODES) ? g_cnt[idx] : 0;
    sh[t] = v;
    __syncthreads();
#pragma unroll
    for (int off = 1; off < SCAN_BLK; off <<= 1) {
        int x = (t >= off) ? sh[t - off] : 0;
        __syncthreads();
        sh[t] += x;
        __syncthreads();
    }
    if (idx < N_NODES) g_off[idx] = sh[t] - v;
    if (t == SCAN_BLK - 1) g_bsum[blockIdx.x] = sh[t];
}

__global__ void scan2_kernel() {
    __shared__ int sh[128];
    int t = threadIdx.x;
    int v = (t < N_SBLK) ? g_bsum[t] : 0;
    sh[t] = v;
    __syncthreads();
#pragma unroll
    for (int off = 1; off < 128; off <<= 1) {
        int x = (t >= off) ? sh[t - off] : 0;
        __syncthreads();
        sh[t] += x;
        __syncthreads();
    }
    if (t < N_SBLK) g_bsum[t] = sh[t] - v;
    if (t == 127) g_off[N_NODES] = sh[127];
}

__global__ void scan3_kernel() {
    int idx = blockIdx.x * SCAN_BLK + threadIdx.x;
    if (idx >= N_NODES) return;
    int o = g_off[idx] + g_bsum[blockIdx.x];
    g_off[idx] = o;
    g_cur[idx] = o;
}

__global__ void place_kernel(const int* __restrict__ edges,
                             const int* __restrict__ posl) {
    int e = blockIdx.x * blockDim.x + threadIdx.x;
    if (e >= TOTAL_EDGES) return;
    int src  = edges[(size_t)2 * e];
    int tgt  = edges[(size_t)2 * e + 1];
    int pos  = posl[e];
    int type = e / M_PER_TYPE;
    int p = atomicAdd(&g_cur[tgt], 1);
    g_sorted[p] = ((uint32_t)src << 12) | ((uint32_t)type << 9) | (uint32_t)pos;
}

// ---------------- GEMM: cp.async double-buffered, pre-split bf16 ------------
// buffer layout (halves): Ah[128][40] Al[128][40] Bh[64][40] Bl[64][40]
#define OFF_AH 0
#define OFF_AL 5120
#define OFF_BH 10240
#define OFF_BL 12800
#define BUF_HALVES 15360
#define SMEM_GEMM_BYTES (2 * BUF_HALVES * 2)   /* 61440 */

__device__ __forceinline__ uint32_t smem_u32(const void* p) {
    uint32_t a;
    asm("{ .reg .u64 t; cvta.to.shared.u64 t, %1; cvt.u32.u64 %0, t; }"
        : "=r"(a) : "l"(p));
    return a;
}
__device__ __forceinline__ void cp16(uint32_t dst, const void* src) {
    asm volatile("cp.async.ca.shared.global [%0], [%1], 16;"
                 :: "r"(dst), "l"(src));
}
__device__ __forceinline__ void cp_commit() {
    asm volatile("cp.async.commit_group;" ::: "memory");
}
template <int N>
__device__ __forceinline__ void cp_wait() {
    asm volatile("cp.async.wait_group %0;" :: "n"(N) : "memory");
}
__device__ __forceinline__ void mma16(float* d, const uint32_t* a, const uint32_t* b) {
    asm volatile(
        "mma.sync.aligned.m16n8k16.row.col.f32.bf16.bf16.f32 "
        "{%0,%1,%2,%3}, {%4,%5,%6,%7}, {%8,%9}, {%0,%1,%2,%3};"
        : "+f"(d[0]), "+f"(d[1]), "+f"(d[2]), "+f"(d[3])
        : "r"(a[0]), "r"(a[1]), "r"(a[2]), "r"(a[3]), "r"(b[0]), "r"(b[1]));
}

__global__ __launch_bounds__(256, 2)
void gemm_kernel(const float* __restrict__ bias) {
    extern __shared__ __nv_bfloat16 sm[];
    const uint32_t sb = smem_u32(sm);
    const int tid  = threadIdx.x;
    const int lane = tid & 31;
    const int wid  = tid >> 5;
    const int wm   = (wid & 3) * 32;
    const int wn   = (wid >> 2) * 32;
    const int mBase = blockIdx.y * 128;    // < 100096 = N_PAD, no guards needed
    const int nBase = blockIdx.x * 64;

    // stage one 32-K chunk (A 128x32 hi/lo + B 64x32 hi/lo) into buffer `buf`
    auto stage = [&](int buf, int kc) {
        uint32_t base = sb + buf * (BUF_HALVES * 2);
#pragma unroll
        for (int t6 = 0; t6 < 6; t6++) {
            int t = tid + t6 * 256;
            if (t < 512) {
                int r = t >> 2, c = t & 3;
                cp16(base + (OFF_AH + r * 40) * 2 + c * 16,
                     g_Ahi + (size_t)(mBase + r) * DIM + kc * 32 + c * 8);
            } else if (t < 1024) {
                int i = t - 512, r = i >> 2, c = i & 3;
                cp16(base + (OFF_AL + r * 40) * 2 + c * 16,
                     g_Alo + (size_t)(mBase + r) * DIM + kc * 32 + c * 8);
            } else if (t < 1280) {
                int i = t - 1024, r = i >> 2, c = i & 3;
                cp16(base + (OFF_BH + r * 40) * 2 + c * 16,
                     g_Whi + (size_t)(nBase + r) * DIM + kc * 32 + c * 8);
            } else {
                int i = t - 1280, r = i >> 2, c = i & 3;
                cp16(base + (OFF_BL + r * 40) * 2 + c * 16,
                     g_Wlo + (size_t)(nBase + r) * DIM + kc * 32 + c * 8);
            }
        }
    };

    float acc[2][4][4];
#pragma unroll
    for (int i = 0; i < 2; i++)
#pragma unroll
        for (int j = 0; j < 4; j++)
#pragma unroll
            for (int k = 0; k < 4; k++) acc[i][j][k] = 0.f;

    stage(0, 0);
    cp_commit();

    int buf = 0;
    for (int kc = 0; kc < 8; kc++) {
        if (kc < 7) {
            stage(buf ^ 1, kc + 1);
            cp_commit();
            cp_wait<1>();           // chunk kc landed (kc+1 still in flight)
        } else {
            cp_wait<0>();
        }
        __syncthreads();

        const __nv_bfloat16* Abh = sm + buf * BUF_HALVES + OFF_AH;
        const __nv_bfloat16* Abl = sm + buf * BUF_HALVES + OFF_AL;
        const __nv_bfloat16* Bbh = sm + buf * BUF_HALVES + OFF_BH;
        const __nv_bfloat16* Bbl = sm + buf * BUF_HALVES + OFF_BL;

#pragma unroll
        for (int kk = 0; kk < 32; kk += 16) {
            const int cA = kk + (lane & 3) * 2;
            uint32_t ah[2][4], al[2][4];
#pragma unroll
            for (int mt = 0; mt < 2; mt++) {
                const __nv_bfloat16* r0h = Abh + (wm + mt * 16 + (lane >> 2)) * 40;
                const __nv_bfloat16* r0l = Abl + (wm + mt * 16 + (lane >> 2)) * 40;
                ah[mt][0] = *reinterpret_cast<const uint32_t*>(r0h + cA);
                ah[mt][1] = *reinterpret_cast<const uint32_t*>(r0h + 8 * 40 + cA);
                ah[mt][2] = *reinterpret_cast<const uint32_t*>(r0h + cA + 8);
                ah[mt][3] = *reinterpret_cast<const uint32_t*>(r0h + 8 * 40 + cA + 8);
                al[mt][0] = *reinterpret_cast<const uint32_t*>(r0l + cA);
                al[mt][1] = *reinterpret_cast<const uint32_t*>(r0l + 8 * 40 + cA);
                al[mt][2] = *reinterpret_cast<const uint32_t*>(r0l + cA + 8);
                al[mt][3] = *reinterpret_cast<const uint32_t*>(r0l + 8 * 40 + cA + 8);
            }
            uint32_t bh[4][2], bl[4][2];
#pragma unroll
            for (int nt = 0; nt < 4; nt++) {
                const __nv_bfloat16* n0h = Bbh + (wn + nt * 8 + (lane >> 2)) * 40;
                const __nv_bfloat16* n0l = Bbl + (wn + nt * 8 + (lane >> 2)) * 40;
                bh[nt][0] = *reinterpret_cast<const uint32_t*>(n0h + cA);
                bh[nt][1] = *reinterpret_cast<const uint32_t*>(n0h + cA + 8);
                bl[nt][0] = *reinterpret_cast<const uint32_t*>(n0l + cA);
                bl[nt][1] = *reinterpret_cast<const uint32_t*>(n0l + cA + 8);
            }
#pragma unroll
            for (int mt = 0; mt < 2; mt++)
#pragma unroll
                for (int nt = 0; nt < 4; nt++) {
                    mma16(acc[mt][nt], ah[mt], bh[nt]);
                    mma16(acc[mt][nt], ah[mt], bl[nt]);
                    mma16(acc[mt][nt], al[mt], bh[nt]);
                }
        }
        __syncthreads();            // buffer free before restage
        buf ^= 1;
    }

    // ---- epilogue: +bias, store fp16
#pragma unroll
    for (int mt = 0; mt < 2; mt++) {
#pragma unroll
        for (int nt = 0; nt < 4; nt++) {
            int row = mBase + wm + mt * 16 + (lane >> 2);
            int col = nBase + wn + nt * 8 + 2 * (lane & 3);
            float b0 = bias[col], b1 = bias[col + 1];
            if (row < N_NODES) {
                __half2 h = __floats2half2_rn(acc[mt][nt][0] + b0, acc[mt][nt][1] + b1);
                *reinterpret_cast<__half2*>(&g_proph[(size_t)row * NBIG + col]) = h;
            }
            if (row + 8 < N_NODES) {
                __half2 h = __floats2half2_rn(acc[mt][nt][2] + b0, acc[mt][nt][3] + b1);
                *reinterpret_cast<__half2*>(&g_proph[(size_t)(row + 8) * NBIG + col]) = h;
            }
        }
    }
}

// ---------------- message: warp per target, 2-way unrolled fp16 gather ------
__global__ __launch_bounds__(256)
void message_kernel(float* __restrict__ out) {
    int t    = (blockIdx.x * blockDim.x + threadIdx.x) >> 5;
    int lane = threadIdx.x & 31;
    if (t >= N_NODES) return;

    const int s0 = g_off[t];
    const int s1 = g_off[t + 1];

    float4 a0 = make_float4(0.f, 0.f, 0.f, 0.f);
    float4 a1 = make_float4(0.f, 0.f, 0.f, 0.f);

    int e = s0;
    for (; e + 1 < s1; e += 2) {
        uint32_t c0 = g_sorted[e], c1 = g_sorted[e + 1];
        int src0 = c0 >> 12, type0 = (c0 >> 9) & 7, pos0 = c0 & 511;
        int src1 = c1 >> 12, type1 = (c1 >> 9) & 7, pos1 = c1 & 511;

        const uint4* p0 = reinterpret_cast<const uint4*>(
            g_proph + (size_t)src0 * NBIG + type0 * DIM) + lane;
        const uint4* p1 = reinterpret_cast<const uint4*>(
            g_proph + (size_t)src1 * NBIG + type1 * DIM) + lane;
        uint4 v0 = __ldg(p0);
        uint4 v1 = __ldg(p1);
        const float4* ga = reinterpret_cast<const float4*>(
            g_gating + (size_t)pos0 * DIM) + lane * 2;
        const float4* gb = reinterpret_cast<const float4*>(
            g_gating + (size_t)pos1 * DIM) + lane * 2;
        float4 ga0 = __ldg(ga), ga1 = __ldg(ga + 1);
        float4 gb0 = __ldg(gb), gb1 = __ldg(gb + 1);

        float2 f;
        f = __half22float2(*reinterpret_cast<__half2*>(&v0.x));
        a0.x += f.x * ga0.x; a0.y += f.y * ga0.y;
        f = __half22float2(*reinterpret_cast<__half2*>(&v0.y));
        a0.z += f.x * ga0.z; a0.w += f.y * ga0.w;
        f = __half22float2(*reinterpret_cast<__half2*>(&v0.z));
        a1.x += f.x * ga1.x; a1.y += f.y * ga1.y;
        f = __half22float2(*reinterpret_cast<__half2*>(&v0.w));
        a1.z += f.x * ga1.z; a1.w += f.y * ga1.w;

        f = __half22float2(*reinterpret_cast<__half2*>(&v1.x));
        a0.x += f.x * gb0.x; a0.y += f.y * gb0.y;
        f = __half22float2(*reinterpret_cast<__half2*>(&v1.y));
        a0.z += f.x * gb0.z; a0.w += f.y * gb0.w;
        f = __half22float2(*reinterpret_cast<__half2*>(&v1.z));
        a1.x += f.x * gb1.x; a1.y += f.y * gb1.y;
        f = __half22float2(*reinterpret_cast<__half2*>(&v1.w));
        a1.z += f.x * gb1.z; a1.w += f.y * gb1.w;
    }
    if (e < s1) {
        uint32_t c0 = g_sorted[e];
        int src0 = c0 >> 12, type0 = (c0 >> 9) & 7, pos0 = c0 & 511;
        const uint4* p0 = reinterpret_cast<const uint4*>(
            g_proph + (size_t)src0 * NBIG + type0 * DIM) + lane;
        uint4 v0 = __ldg(p0);
        const float4* ga = reinterpret_cast<const float4*>(
            g_gating + (size_t)pos0 * DIM) + lane * 2;
        float4 ga0 = __ldg(ga), ga1 = __ldg(ga + 1);
        float2 f;
        f = __half22float2(*reinterpret_cast<__half2*>(&v0.x));
        a0.x += f.x * ga0.x; a0.y += f.y * ga0.y;
        f = __half22float2(*reinterpret_cast<__half2*>(&v0.y));
        a0.z += f.x * ga0.z; a0.w += f.y * ga0.w;
        f = __half22float2(*reinterpret_cast<__half2*>(&v0.z));
        a1.x += f.x * ga1.x; a1.y += f.y * ga1.y;
        f = __half22float2(*reinterpret_cast<__half2*>(&v0.w));
        a1.z += f.x * ga1.z; a1.w += f.y * ga1.w;
    }

    int deg = s1 - s0;
    float div = ((deg == 0) ? 1.0f : (float)deg) + 1e-8f;
    float s = 1.0f / div;
    a0.x *= s; a0.y *= s; a0.z *= s; a0.w *= s;
    a1.x *= s; a1.y *= s; a1.z *= s; a1.w *= s;

    float4* dst = reinterpret_cast<float4*>(out + (size_t)t * DIM) + lane * 2;
    dst[0] = a0;
    dst[1] = a1;
}

// ---------------- launch ----------------------------------------------------
extern "C" void kernel_launch(void* const* d_in, const int* in_sizes, int n_in,
                              void* d_out, int out_size) {
    const float* node_states = (const float*)d_in[0];
    const float* W    = (const float*)d_in[1];
    const float* b    = (const float*)d_in[2];
    const float* Wp   = (const float*)d_in[3];
    const float* bp   = (const float*)d_in[4];
    const int*   edges = (const int*)d_in[5];
    const int*   posl  = (const int*)d_in[6];
    float* out = (float*)d_out;

    cudaFuncSetAttribute(gemm_kernel,
                         cudaFuncAttributeMaxDynamicSharedMemorySize,
                         SMEM_GEMM_BYTES);

    convertA_kernel<<<(N_NODES * DIM + 255) / 256, 256>>>(node_states);
    convertW_kernel<<<(NBIG * DIM + 255) / 256, 256>>>(W);
    gating_kernel<<<POS_TAB, 256>>>(Wp, bp);                 // + zero hist
    hist_kernel<<<(TOTAL_EDGES + 255) / 256, 256>>>(edges);
    scan1_kernel<<<N_SBLK, SCAN_BLK>>>();
    scan2_kernel<<<1, 128>>>();
    scan3_kernel<<<N_SBLK, SCAN_BLK>>>();
    place_kernel<<<(TOTAL_EDGES + 255) / 256, 256>>>(edges, posl);

    dim3 gg(NBIG / 64, N_PAD / 128);
    gemm_kernel<<<gg, 256, SMEM_GEMM_BYTES>>>(b);

    message_kernel<<<(N_NODES * 32 + 255) / 256, 256>>>(out);
}

// round 12
// speedup vs baseline: 2.0337x; 1.4214x over previous
#include <cuda_runtime.h>
#include <cuda_fp16.h>
#include <cstdint>
#include <cstddef>

#define N_NODES     100000
#define N_PAD       100096            /* 782 * 128 */
#define DIM         256
#define N_ET        6
#define M_PER_TYPE  400000
#define TOTAL_EDGES (N_ET * M_PER_TYPE)
#define NBIG        (N_ET * DIM)      /* 1536 */
#define POS_TAB     512
#define SCAN_BLK    1024
#define N_SBLK      ((N_NODES + SCAN_BLK - 1) / SCAN_BLK)   /* 98 */
#define CNT_PAD     (N_SBLK * SCAN_BLK)

// ---------------- device scratch (sanctioned: __device__ globals) ----------
__device__ __half   g_proph[(size_t)N_NODES * NBIG]; // 307.2 MB
__device__ float    g_gating[POS_TAB * DIM];
__device__ int      g_cnt[CNT_PAD];
__device__ int      g_off[N_NODES + 1];
__device__ int      g_cur[N_NODES];
__device__ int      g_bsum[N_SBLK + 1];
__device__ uint32_t g_sorted[TOTAL_EDGES];
__device__ __half   g_Ah[(size_t)N_PAD * DIM];       // 51.2 MB (pad rows stay 0)
__device__ __half   g_Wh[NBIG * DIM];                // 768 KB

// ---------------- pre-convert passes ----------------------------------------
__global__ void convertA_kernel(const float* __restrict__ A) {
    int i = blockIdx.x * blockDim.x + threadIdx.x;
    if (i >= N_NODES * DIM) return;
    g_Ah[i] = __float2half_rn(A[i]);
}
__global__ void convertW_kernel(const float* __restrict__ W) {
    int i = blockIdx.x * blockDim.x + threadIdx.x;
    if (i >= NBIG * DIM) return;
    g_Wh[i] = __float2half_rn(W[i]);
}

// ---------------- gating + zero counters ------------------------------------
__global__ void gating_kernel(const float* __restrict__ Wp,
                              const float* __restrict__ bp) {
    __shared__ float emb[DIM];
    const int p = blockIdx.x;
    const int t = threadIdx.x;
    if (t < 127) {
        float y    = (float)(2 * t) / 254.0f;
        float invf = 1.0f / powf(10000.0f, y);
        float ang  = (float)p * invf;
        emb[t]       = sinf(ang);
        emb[t + 127] = cosf(ang);
    } else if (t >= 254) {
        emb[t] = 0.0f;
    }
    int bi = blockIdx.x * blockDim.x + t;
    if (bi < CNT_PAD) g_cnt[bi] = 0;
    __syncthreads();

    float s = bp[t];
    const float* w = Wp + (size_t)t * DIM;
#pragma unroll 8
    for (int k = 0; k < DIM; ++k) s += emb[k] * w[k];
    g_gating[p * DIM + t] = 2.0f / (1.0f + expf(-s));
}

// ---------------- counting sort ---------------------------------------------
__global__ void hist_kernel(const int* __restrict__ edges) {
    int e = blockIdx.x * blockDim.x + threadIdx.x;
    if (e >= TOTAL_EDGES) return;
    atomicAdd(&g_cnt[edges[(size_t)2 * e + 1]], 1);
}

__global__ void scan1_kernel() {
    __shared__ int sh[SCAN_BLK];
    int t   = threadIdx.x;
    int idx = blockIdx.x * SCAN_BLK + t;
    int v   = (idx < N_NODES) ? g_cnt[idx] : 0;
    sh[t] = v;
    __syncthreads();
#pragma unroll
    for (int off = 1; off < SCAN_BLK; off <<= 1) {
        int x = (t >= off) ? sh[t - off] : 0;
        __syncthreads();
        sh[t] += x;
        __syncthreads();
    }
    if (idx < N_NODES) g_off[idx] = sh[t] - v;
    if (t == SCAN_BLK - 1) g_bsum[blockIdx.x] = sh[t];
}

__global__ void scan2_kernel() {
    __shared__ int sh[128];
    int t = threadIdx.x;
    int v = (t < N_SBLK) ? g_bsum[t] : 0;
    sh[t] = v;
    __syncthreads();
#pragma unroll
    for (int off = 1; off < 128; off <<= 1) {
        int x = (t >= off) ? sh[t - off] : 0;
        __syncthreads();
        sh[t] += x;
        __syncthreads();
    }
    if (t < N_SBLK) g_bsum[t] = sh[t] - v;
    if (t == 127) g_off[N_NODES] = sh[127];
}

__global__ void scan3_kernel() {
    int idx = blockIdx.x * SCAN_BLK + threadIdx.x;
    if (idx >= N_NODES) return;
    int o = g_off[idx] + g_bsum[blockIdx.x];
    g_off[idx] = o;
    g_cur[idx] = o;
}

__global__ void place_kernel(const int* __restrict__ edges,
                             const int* __restrict__ posl) {
    int e = blockIdx.x * blockDim.x + threadIdx.x;
    if (e >= TOTAL_EDGES) return;
    int src  = edges[(size_t)2 * e];
    int tgt  = edges[(size_t)2 * e + 1];
    int pos  = posl[e];
    int type = e / M_PER_TYPE;
    int p = atomicAdd(&g_cur[tgt], 1);
    g_sorted[p] = ((uint32_t)src << 12) | ((uint32_t)type << 9) | (uint32_t)pos;
}

// ---------------- GEMM: single-pass fp16 mma, cp.async double-buffered ------
// buffer layout (halves): Ah[128][40] Bh[64][40]
#define OFF_AH 0
#define OFF_BH 5120
#define BUF_HALVES 7680
#define SMEM_GEMM_BYTES (2 * BUF_HALVES * 2)   /* 30720 */

__device__ __forceinline__ uint32_t smem_u32(const void* p) {
    uint32_t a;
    asm("{ .reg .u64 t; cvta.to.shared.u64 t, %1; cvt.u32.u64 %0, t; }"
        : "=r"(a) : "l"(p));
    return a;
}
__device__ __forceinline__ void cp16(uint32_t dst, const void* src) {
    asm volatile("cp.async.ca.shared.global [%0], [%1], 16;"
                 :: "r"(dst), "l"(src));
}
__device__ __forceinline__ void cp_commit() {
    asm volatile("cp.async.commit_group;" ::: "memory");
}
template <int N>
__device__ __forceinline__ void cp_wait() {
    asm volatile("cp.async.wait_group %0;" :: "n"(N) : "memory");
}
__device__ __forceinline__ void mmah16(float* d, const uint32_t* a, const uint32_t* b) {
    asm volatile(
        "mma.sync.aligned.m16n8k16.row.col.f32.f16.f16.f32 "
        "{%0,%1,%2,%3}, {%4,%5,%6,%7}, {%8,%9}, {%0,%1,%2,%3};"
        : "+f"(d[0]), "+f"(d[1]), "+f"(d[2]), "+f"(d[3])
        : "r"(a[0]), "r"(a[1]), "r"(a[2]), "r"(a[3]), "r"(b[0]), "r"(b[1]));
}

__global__ __launch_bounds__(256, 2)
void gemm_kernel(const float* __restrict__ bias) {
    extern __shared__ __half sm[];
    const uint32_t sb = smem_u32(sm);
    const int tid  = threadIdx.x;
    const int lane = tid & 31;
    const int wid  = tid >> 5;
    const int wm   = (wid & 3) * 32;
    const int wn   = (wid >> 2) * 32;
    const int mBase = blockIdx.y * 128;    // < N_PAD, pad rows are zero
    const int nBase = blockIdx.x * 64;

    // stage one 32-K chunk (A 128x32 + B 64x32 fp16) into buffer `buf`
    auto stage = [&](int buf, int kc) {
        uint32_t base = sb + buf * (BUF_HALVES * 2);
#pragma unroll
        for (int t3 = 0; t3 < 3; t3++) {
            int t = tid + t3 * 256;
            if (t < 512) {
                int r = t >> 2, c = t & 3;
                cp16(base + (OFF_AH + r * 40) * 2 + c * 16,
                     g_Ah + (size_t)(mBase + r) * DIM + kc * 32 + c * 8);
            } else {
                int i = t - 512, r = i >> 2, c = i & 3;
                cp16(base + (OFF_BH + r * 40) * 2 + c * 16,
                     g_Wh + (size_t)(nBase + r) * DIM + kc * 32 + c * 8);
            }
        }
    };

    float acc[2][4][4];
#pragma unroll
    for (int i = 0; i < 2; i++)
#pragma unroll
        for (int j = 0; j < 4; j++)
#pragma unroll
            for (int k = 0; k < 4; k++) acc[i][j][k] = 0.f;

    stage(0, 0);
    cp_commit();

    int buf = 0;
    for (int kc = 0; kc < 8; kc++) {
        if (kc < 7) {
            stage(buf ^ 1, kc + 1);
            cp_commit();
            cp_wait<1>();           // chunk kc landed, kc+1 in flight
        } else {
            cp_wait<0>();
        }
        __syncthreads();

        const __half* Abh = sm + buf * BUF_HALVES + OFF_AH;
        const __half* Bbh = sm + buf * BUF_HALVES + OFF_BH;

#pragma unroll
        for (int kk = 0; kk < 32; kk += 16) {
            const int cA = kk + (lane & 3) * 2;
            uint32_t ah[2][4];
#pragma unroll
            for (int mt = 0; mt < 2; mt++) {
                const __half* r0 = Abh + (wm + mt * 16 + (lane >> 2)) * 40;
                ah[mt][0] = *reinterpret_cast<const uint32_t*>(r0 + cA);
                ah[mt][1] = *reinterpret_cast<const uint32_t*>(r0 + 8 * 40 + cA);
                ah[mt][2] = *reinterpret_cast<const uint32_t*>(r0 + cA + 8);
                ah[mt][3] = *reinterpret_cast<const uint32_t*>(r0 + 8 * 40 + cA + 8);
            }
            uint32_t bh[4][2];
#pragma unroll
            for (int nt = 0; nt < 4; nt++) {
                const __half* n0 = Bbh + (wn + nt * 8 + (lane >> 2)) * 40;
                bh[nt][0] = *reinterpret_cast<const uint32_t*>(n0 + cA);
                bh[nt][1] = *reinterpret_cast<const uint32_t*>(n0 + cA + 8);
            }
#pragma unroll
            for (int mt = 0; mt < 2; mt++)
#pragma unroll
                for (int nt = 0; nt < 4; nt++)
                    mmah16(acc[mt][nt], ah[mt], bh[nt]);
        }
        __syncthreads();            // buffer free before restage
        buf ^= 1;
    }

    // ---- epilogue: +bias, store fp16
#pragma unroll
    for (int mt = 0; mt < 2; mt++) {
#pragma unroll
        for (int nt = 0; nt < 4; nt++) {
            int row = mBase + wm + mt * 16 + (lane >> 2);
            int col = nBase + wn + nt * 8 + 2 * (lane & 3);
            float b0 = bias[col], b1 = bias[col + 1];
            if (row < N_NODES) {
                __half2 h = __floats2half2_rn(acc[mt][nt][0] + b0, acc[mt][nt][1] + b1);
                *reinterpret_cast<__half2*>(&g_proph[(size_t)row * NBIG + col]) = h;
            }
            if (row + 8 < N_NODES) {
                __half2 h = __floats2half2_rn(acc[mt][nt][2] + b0, acc[mt][nt][3] + b1);
                *reinterpret_cast<__half2*>(&g_proph[(size_t)(row + 8) * NBIG + col]) = h;
            }
        }
    }
}

// ---------------- message: warp per target, 2-way unrolled fp16 gather ------
__global__ __launch_bounds__(256)
void message_kernel(float* __restrict__ out) {
    int t    = (blockIdx.x * blockDim.x + threadIdx.x) >> 5;
    int lane = threadIdx.x & 31;
    if (t >= N_NODES) return;

    const int s0 = g_off[t];
    const int s1 = g_off[t + 1];

    float4 a0 = make_float4(0.f, 0.f, 0.f, 0.f);
    float4 a1 = make_float4(0.f, 0.f, 0.f, 0.f);

    int e = s0;
    for (; e + 1 < s1; e += 2) {
        uint32_t c0 = g_sorted[e], c1 = g_sorted[e + 1];
        int src0 = c0 >> 12, type0 = (c0 >> 9) & 7, pos0 = c0 & 511;
        int src1 = c1 >> 12, type1 = (c1 >> 9) & 7, pos1 = c1 & 511;

        const uint4* p0 = reinterpret_cast<const uint4*>(
            g_proph + (size_t)src0 * NBIG + type0 * DIM) + lane;
        const uint4* p1 = reinterpret_cast<const uint4*>(
            g_proph + (size_t)src1 * NBIG + type1 * DIM) + lane;
        uint4 v0 = __ldg(p0);
        uint4 v1 = __ldg(p1);
        const float4* ga = reinterpret_cast<const float4*>(
            g_gating + (size_t)pos0 * DIM) + lane * 2;
        const float4* gb = reinterpret_cast<const float4*>(
            g_gating + (size_t)pos1 * DIM) + lane * 2;
        float4 ga0 = __ldg(ga), ga1 = __ldg(ga + 1);
        float4 gb0 = __ldg(gb), gb1 = __ldg(gb + 1);

        float2 f;
        f = __half22float2(*reinterpret_cast<__half2*>(&v0.x));
        a0.x += f.x * ga0.x; a0.y += f.y * ga0.y;
        f = __half22float2(*reinterpret_cast<__half2*>(&v0.y));
        a0.z += f.x * ga0.z; a0.w += f.y * ga0.w;
        f = __half22float2(*reinterpret_cast<__half2*>(&v0.z));
        a1.x += f.x * ga1.x; a1.y += f.y * ga1.y;
        f = __half22float2(*reinterpret_cast<__half2*>(&v0.w));
        a1.z += f.x * ga1.z; a1.w += f.y * ga1.w;

        f = __half22float2(*reinterpret_cast<__half2*>(&v1.x));
        a0.x += f.x * gb0.x; a0.y += f.y * gb0.y;
        f = __half22float2(*reinterpret_cast<__half2*>(&v1.y));
        a0.z += f.x * gb0.z; a0.w += f.y * gb0.w;
        f = __half22float2(*reinterpret_cast<__half2*>(&v1.z));
        a1.x += f.x * gb1.x; a1.y += f.y * gb1.y;
        f = __half22float2(*reinterpret_cast<__half2*>(&v1.w));
        a1.z += f.x * gb1.z; a1.w += f.y * gb1.w;
    }
    if (e < s1) {
        uint32_t c0 = g_sorted[e];
        int src0 = c0 >> 12, type0 = (c0 >> 9) & 7, pos0 = c0 & 511;
        const uint4* p0 = reinterpret_cast<const uint4*>(
            g_proph + (size_t)src0 * NBIG + type0 * DIM) + lane;
        uint4 v0 = __ldg(p0);
        const float4* ga = reinterpret_cast<const float4*>(
            g_gating + (size_t)pos0 * DIM) + lane * 2;
        float4 ga0 = __ldg(ga), ga1 = __ldg(ga + 1);
        float2 f;
        f = __half22float2(*reinterpret_cast<__half2*>(&v0.x));
        a0.x += f.x * ga0.x; a0.y += f.y * ga0.y;
        f = __half22float2(*reinterpret_cast<__half2*>(&v0.y));
        a0.z += f.x * ga0.z; a0.w += f.y * ga0.w;
        f = __half22float2(*reinterpret_cast<__half2*>(&v0.z));
        a1.x += f.x * ga1.x; a1.y += f.y * ga1.y;
        f = __half22float2(*reinterpret_cast<__half2*>(&v0.w));
        a1.z += f.x * ga1.z; a1.w += f.y * ga1.w;
    }

    int deg = s1 - s0;
    float div = ((deg == 0) ? 1.0f : (float)deg) + 1e-8f;
    float s = 1.0f / div;
    a0.x *= s; a0.y *= s; a0.z *= s; a0.w *= s;
    a1.x *= s; a1.y *= s; a1.z *= s; a1.w *= s;

    float4* dst = reinterpret_cast<float4*>(out + (size_t)t * DIM) + lane * 2;
    dst[0] = a0;
    dst[1] = a1;
}

// ---------------- launch ----------------------------------------------------
extern "C" void kernel_launch(void* const* d_in, const int* in_sizes, int n_in,
                              void* d_out, int out_size) {
    const float* node_states = (const float*)d_in[0];
    const float* W    = (const float*)d_in[1];
    const float* b    = (const float*)d_in[2];
    const float* Wp   = (const float*)d_in[3];
    const float* bp   = (const float*)d_in[4];
    const int*   edges = (const int*)d_in[5];
    const int*   posl  = (const int*)d_in[6];
    float* out = (float*)d_out;

    cudaFuncSetAttribute(gemm_kernel,
                         cudaFuncAttributeMaxDynamicSharedMemorySize,
                         SMEM_GEMM_BYTES);

    convertA_kernel<<<(N_NODES * DIM + 255) / 256, 256>>>(node_states);
    convertW_kernel<<<(NBIG * DIM + 255) / 256, 256>>>(W);
    gating_kernel<<<POS_TAB, 256>>>(Wp, bp);                 // + zero hist
    hist_kernel<<<(TOTAL_EDGES + 255) / 256, 256>>>(edges);
    scan1_kernel<<<N_SBLK, SCAN_BLK>>>();
    scan2_kernel<<<1, 128>>>();
    scan3_kernel<<<N_SBLK, SCAN_BLK>>>();
    place_kernel<<<(TOTAL_EDGES + 255) / 256, 256>>>(edges, posl);

    dim3 gg(NBIG / 64, N_PAD / 128);
    gemm_kernel<<<gg, 256, SMEM_GEMM_BYTES>>>(b);

    message_kernel<<<(N_NODES * 32 + 255) / 256, 256>>>(out);
}

// round 13
// speedup vs baseline: 2.2363x; 1.0996x over previous
#include <cuda_runtime.h>
#include <cuda_fp16.h>
#include <cstdint>
#include <cstddef>

#define N_NODES     100000
#define N_PAD       100096            /* 782 * 128 */
#define DIM         256
#define N_ET        6
#define M_PER_TYPE  400000
#define TOTAL_EDGES (N_ET * M_PER_TYPE)
#define NBIG        (N_ET * DIM)      /* 1536 */
#define POS_TAB     512
#define SCAN_BLK    1024
#define N_SBLK      ((N_NODES + SCAN_BLK - 1) / SCAN_BLK)   /* 98 */
#define CNT_PAD     (N_SBLK * SCAN_BLK)

// ---------------- device scratch (sanctioned: __device__ globals) ----------
__device__ __half   g_proph[(size_t)N_NODES * NBIG]; // 307.2 MB
__device__ float    g_gating[POS_TAB * DIM];
__device__ int      g_cnt[CNT_PAD];
__device__ int      g_off[N_NODES + 1];
__device__ int      g_cur[N_NODES];
__device__ int      g_bsum[N_SBLK + 1];
__device__ uint32_t g_sorted[TOTAL_EDGES];
__device__ __half   g_Ah[(size_t)N_PAD * DIM];       // 51.2 MB (pad rows stay 0)
__device__ __half   g_Wh[NBIG * DIM];                // 768 KB

// ---------------- fused fp16 convert pass ------------------------------------
__global__ void convert_kernel(const float* __restrict__ A,
                               const float* __restrict__ W) {
    int i = blockIdx.x * blockDim.x + threadIdx.x;
    const int nA = N_NODES * DIM;
    if (i < nA) {
        g_Ah[i] = __float2half_rn(A[i]);
    } else {
        int j = i - nA;
        if (j < NBIG * DIM) g_Wh[j] = __float2half_rn(W[j]);
    }
}

// ---------------- gating + zero counters ------------------------------------
__global__ void gating_kernel(const float* __restrict__ Wp,
                              const float* __restrict__ bp) {
    __shared__ float emb[DIM];
    const int p = blockIdx.x;
    const int t = threadIdx.x;
    if (t < 127) {
        float y    = (float)(2 * t) / 254.0f;
        float invf = 1.0f / powf(10000.0f, y);
        float ang  = (float)p * invf;
        emb[t]       = sinf(ang);
        emb[t + 127] = cosf(ang);
    } else if (t >= 254) {
        emb[t] = 0.0f;
    }
    int bi = blockIdx.x * blockDim.x + t;
    if (bi < CNT_PAD) g_cnt[bi] = 0;
    __syncthreads();

    float s = bp[t];
    const float* w = Wp + (size_t)t * DIM;
#pragma unroll 8
    for (int k = 0; k < DIM; ++k) s += emb[k] * w[k];
    g_gating[p * DIM + t] = 2.0f / (1.0f + expf(-s));
}

// ---------------- counting sort ---------------------------------------------
__global__ void hist_kernel(const int* __restrict__ edges) {
    int e = blockIdx.x * blockDim.x + threadIdx.x;
    if (e >= TOTAL_EDGES) return;
    atomicAdd(&g_cnt[edges[(size_t)2 * e + 1]], 1);
}

__global__ void scan1_kernel() {
    __shared__ int sh[SCAN_BLK];
    int t   = threadIdx.x;
    int idx = blockIdx.x * SCAN_BLK + t;
    int v   = (idx < N_NODES) ? g_cnt[idx] : 0;
    sh[t] = v;
    __syncthreads();
#pragma unroll
    for (int off = 1; off < SCAN_BLK; off <<= 1) {
        int x = (t >= off) ? sh[t - off] : 0;
        __syncthreads();
        sh[t] += x;
        __syncthreads();
    }
    if (idx < N_NODES) g_off[idx] = sh[t] - v;
    if (t == SCAN_BLK - 1) g_bsum[blockIdx.x] = sh[t];
}

__global__ void scan2_kernel() {
    __shared__ int sh[128];
    int t = threadIdx.x;
    int v = (t < N_SBLK) ? g_bsum[t] : 0;
    sh[t] = v;
    __syncthreads();
#pragma unroll
    for (int off = 1; off < 128; off <<= 1) {
        int x = (t >= off) ? sh[t - off] : 0;
        __syncthreads();
        sh[t] += x;
        __syncthreads();
    }
    if (t < N_SBLK) g_bsum[t] = sh[t] - v;
    if (t == 127) g_off[N_NODES] = sh[127];
}

__global__ void scan3_kernel() {
    int idx = blockIdx.x * SCAN_BLK + threadIdx.x;
    if (idx >= N_NODES) return;
    int o = g_off[idx] + g_bsum[blockIdx.x];
    g_off[idx] = o;
    g_cur[idx] = o;
}

__global__ void place_kernel(const int* __restrict__ edges,
                             const int* __restrict__ posl) {
    int e = blockIdx.x * blockDim.x + threadIdx.x;
    if (e >= TOTAL_EDGES) return;
    int src  = edges[(size_t)2 * e];
    int tgt  = edges[(size_t)2 * e + 1];
    int pos  = posl[e];
    int type = e / M_PER_TYPE;
    int p = atomicAdd(&g_cur[tgt], 1);
    g_sorted[p] = ((uint32_t)src << 12) | ((uint32_t)type << 9) | (uint32_t)pos;
}

// ---------------- GEMM: fp16 mma, 128x128 tile, cp.async double-buffered ----
// buffer layout (halves): Ah[128][40] Bh[128][40]
#define OFF_AH 0
#define OFF_BH 5120
#define BUF_HALVES 10240
#define SMEM_GEMM_BYTES (2 * BUF_HALVES * 2)   /* 40960 */

__device__ __forceinline__ uint32_t smem_u32(const void* p) {
    uint32_t a;
    asm("{ .reg .u64 t; cvta.to.shared.u64 t, %1; cvt.u32.u64 %0, t; }"
        : "=r"(a) : "l"(p));
    return a;
}
__device__ __forceinline__ void cp16(uint32_t dst, const void* src) {
    asm volatile("cp.async.ca.shared.global [%0], [%1], 16;"
                 :: "r"(dst), "l"(src));
}
__device__ __forceinline__ void cp_commit() {
    asm volatile("cp.async.commit_group;" ::: "memory");
}
template <int N>
__device__ __forceinline__ void cp_wait() {
    asm volatile("cp.async.wait_group %0;" :: "n"(N) : "memory");
}
__device__ __forceinline__ void mmah16(float* d, const uint32_t* a, const uint32_t* b) {
    asm volatile(
        "mma.sync.aligned.m16n8k16.row.col.f32.f16.f16.f32 "
        "{%0,%1,%2,%3}, {%4,%5,%6,%7}, {%8,%9}, {%0,%1,%2,%3};"
        : "+f"(d[0]), "+f"(d[1]), "+f"(d[2]), "+f"(d[3])
        : "r"(a[0]), "r"(a[1]), "r"(a[2]), "r"(a[3]), "r"(b[0]), "r"(b[1]));
}

__global__ __launch_bounds__(256, 2)
void gemm_kernel(const float* __restrict__ bias) {
    extern __shared__ __half sm[];
    const uint32_t sb = smem_u32(sm);
    const int tid  = threadIdx.x;
    const int lane = tid & 31;
    const int wid  = tid >> 5;
    const int wm   = (wid & 3) * 32;       // warp M base within 128
    const int wn   = (wid >> 2) * 64;      // warp N base within 128
    const int mBase = blockIdx.y * 128;    // < N_PAD, pad rows are zero
    const int nBase = blockIdx.x * 128;

    // stage one 32-K chunk (A 128x32 + B 128x32 fp16) into buffer `buf`
    auto stage = [&](int buf, int kc) {
        uint32_t base = sb + buf * (BUF_HALVES * 2);
#pragma unroll
        for (int t4 = 0; t4 < 4; t4++) {
            int t = tid + t4 * 256;
            if (t < 512) {
                int r = t >> 2, c = t & 3;
                cp16(base + (OFF_AH + r * 40) * 2 + c * 16,
                     g_Ah + (size_t)(mBase + r) * DIM + kc * 32 + c * 8);
            } else {
                int i = t - 512, r = i >> 2, c = i & 3;
                cp16(base + (OFF_BH + r * 40) * 2 + c * 16,
                     g_Wh + (size_t)(nBase + r) * DIM + kc * 32 + c * 8);
            }
        }
    };

    float acc[2][8][4];
#pragma unroll
    for (int i = 0; i < 2; i++)
#pragma unroll
        for (int j = 0; j < 8; j++)
#pragma unroll
            for (int k = 0; k < 4; k++) acc[i][j][k] = 0.f;

    stage(0, 0);
    cp_commit();

    int buf = 0;
    for (int kc = 0; kc < 8; kc++) {
        if (kc < 7) {
            stage(buf ^ 1, kc + 1);
            cp_commit();
            cp_wait<1>();           // chunk kc landed, kc+1 in flight
        } else {
            cp_wait<0>();
        }
        __syncthreads();

        const __half* Abh = sm + buf * BUF_HALVES + OFF_AH;
        const __half* Bbh = sm + buf * BUF_HALVES + OFF_BH;

#pragma unroll
        for (int kk = 0; kk < 32; kk += 16) {
            const int cA = kk + (lane & 3) * 2;
            uint32_t ah[2][4];
#pragma unroll
            for (int mt = 0; mt < 2; mt++) {
                const __half* r0 = Abh + (wm + mt * 16 + (lane >> 2)) * 40;
                ah[mt][0] = *reinterpret_cast<const uint32_t*>(r0 + cA);
                ah[mt][1] = *reinterpret_cast<const uint32_t*>(r0 + 8 * 40 + cA);
                ah[mt][2] = *reinterpret_cast<const uint32_t*>(r0 + cA + 8);
                ah[mt][3] = *reinterpret_cast<const uint32_t*>(r0 + 8 * 40 + cA + 8);
            }
            uint32_t bh[8][2];
#pragma unroll
            for (int nt = 0; nt < 8; nt++) {
                const __half* n0 = Bbh + (wn + nt * 8 + (lane >> 2)) * 40;
                bh[nt][0] = *reinterpret_cast<const uint32_t*>(n0 + cA);
                bh[nt][1] = *reinterpret_cast<const uint32_t*>(n0 + cA + 8);
            }
#pragma unroll
            for (int mt = 0; mt < 2; mt++)
#pragma unroll
                for (int nt = 0; nt < 8; nt++)
                    mmah16(acc[mt][nt], ah[mt], bh[nt]);
        }
        __syncthreads();            // buffer free before restage
        buf ^= 1;
    }

    // ---- epilogue: +bias, store fp16
#pragma unroll
    for (int mt = 0; mt < 2; mt++) {
#pragma unroll
        for (int nt = 0; nt < 8; nt++) {
            int row = mBase + wm + mt * 16 + (lane >> 2);
            int col = nBase + wn + nt * 8 + 2 * (lane & 3);
            float b0 = bias[col], b1 = bias[col + 1];
            if (row < N_NODES) {
                __half2 h = __floats2half2_rn(acc[mt][nt][0] + b0, acc[mt][nt][1] + b1);
                *reinterpret_cast<__half2*>(&g_proph[(size_t)row * NBIG + col]) = h;
            }
            if (row + 8 < N_NODES) {
                __half2 h = __floats2half2_rn(acc[mt][nt][2] + b0, acc[mt][nt][3] + b1);
                *reinterpret_cast<__half2*>(&g_proph[(size_t)(row + 8) * NBIG + col]) = h;
            }
        }
    }
}

// ---------------- message: warp per target, 4-way unrolled fp16 gather ------
__device__ __forceinline__ void acc_rec(uint4 v, float4 g0, float4 g1,
                                        float4& a0, float4& a1) {
    float2 f;
    f = __half22float2(*reinterpret_cast<__half2*>(&v.x));
    a0.x += f.x * g0.x; a0.y += f.y * g0.y;
    f = __half22float2(*reinterpret_cast<__half2*>(&v.y));
    a0.z += f.x * g0.z; a0.w += f.y * g0.w;
    f = __half22float2(*reinterpret_cast<__half2*>(&v.z));
    a1.x += f.x * g1.x; a1.y += f.y * g1.y;
    f = __half22float2(*reinterpret_cast<__half2*>(&v.w));
    a1.z += f.x * g1.z; a1.w += f.y * g1.w;
}

__global__ __launch_bounds__(256)
void message_kernel(float* __restrict__ out) {
    int t    = (blockIdx.x * blockDim.x + threadIdx.x) >> 5;
    int lane = threadIdx.x & 31;
    if (t >= N_NODES) return;

    const int s0 = g_off[t];
    const int s1 = g_off[t + 1];

    float4 a0 = make_float4(0.f, 0.f, 0.f, 0.f);
    float4 a1 = make_float4(0.f, 0.f, 0.f, 0.f);

    int e = s0;
    for (; e + 3 < s1; e += 4) {
        uint32_t c0 = g_sorted[e],     c1 = g_sorted[e + 1];
        uint32_t c2 = g_sorted[e + 2], c3 = g_sorted[e + 3];

        const uint4* p0 = reinterpret_cast<const uint4*>(
            g_proph + (size_t)(c0 >> 12) * NBIG + ((c0 >> 9) & 7) * DIM) + lane;
        const uint4* p1 = reinterpret_cast<const uint4*>(
            g_proph + (size_t)(c1 >> 12) * NBIG + ((c1 >> 9) & 7) * DIM) + lane;
        const uint4* p2 = reinterpret_cast<const uint4*>(
            g_proph + (size_t)(c2 >> 12) * NBIG + ((c2 >> 9) & 7) * DIM) + lane;
        const uint4* p3 = reinterpret_cast<const uint4*>(
            g_proph + (size_t)(c3 >> 12) * NBIG + ((c3 >> 9) & 7) * DIM) + lane;
        uint4 v0 = __ldg(p0);
        uint4 v1 = __ldg(p1);
        uint4 v2 = __ldg(p2);
        uint4 v3 = __ldg(p3);

        const float4* ga = reinterpret_cast<const float4*>(
            g_gating + (size_t)(c0 & 511) * DIM) + lane * 2;
        const float4* gb = reinterpret_cast<const float4*>(
            g_gating + (size_t)(c1 & 511) * DIM) + lane * 2;
        const float4* gc = reinterpret_cast<const float4*>(
            g_gating + (size_t)(c2 & 511) * DIM) + lane * 2;
        const float4* gd = reinterpret_cast<const float4*>(
            g_gating + (size_t)(c3 & 511) * DIM) + lane * 2;
        float4 ga0 = __ldg(ga), ga1 = __ldg(ga + 1);
        float4 gb0 = __ldg(gb), gb1 = __ldg(gb + 1);
        float4 gc0 = __ldg(gc), gc1 = __ldg(gc + 1);
        float4 gd0 = __ldg(gd), gd1 = __ldg(gd + 1);

        acc_rec(v0, ga0, ga1, a0, a1);
        acc_rec(v1, gb0, gb1, a0, a1);
        acc_rec(v2, gc0, gc1, a0, a1);
        acc_rec(v3, gd0, gd1, a0, a1);
    }
    for (; e < s1; ++e) {
        uint32_t c0 = g_sorted[e];
        const uint4* p0 = reinterpret_cast<const uint4*>(
            g_proph + (size_t)(c0 >> 12) * NBIG + ((c0 >> 9) & 7) * DIM) + lane;
        uint4 v0 = __ldg(p0);
        const float4* ga = reinterpret_cast<const float4*>(
            g_gating + (size_t)(c0 & 511) * DIM) + lane * 2;
        float4 ga0 = __ldg(ga), ga1 = __ldg(ga + 1);
        acc_rec(v0, ga0, ga1, a0, a1);
    }

    int deg = s1 - s0;
    float div = ((deg == 0) ? 1.0f : (float)deg) + 1e-8f;
    float s = 1.0f / div;
    a0.x *= s; a0.y *= s; a0.z *= s; a0.w *= s;
    a1.x *= s; a1.y *= s; a1.z *= s; a1.w *= s;

    float4* dst = reinterpret_cast<float4*>(out + (size_t)t * DIM) + lane * 2;
    dst[0] = a0;
    dst[1] = a1;
}

// ---------------- launch ----------------------------------------------------
extern "C" void kernel_launch(void* const* d_in, const int* in_sizes, int n_in,
                              void* d_out, int out_size) {
    const float* node_states = (const float*)d_in[0];
    const float* W    = (const float*)d_in[1];
    const float* b    = (const float*)d_in[2];
    const float* Wp   = (const float*)d_in[3];
    const float* bp   = (const float*)d_in[4];
    const int*   edges = (const int*)d_in[5];
    const int*   posl  = (const int*)d_in[6];
    float* out = (float*)d_out;

    cudaFuncSetAttribute(gemm_kernel,
                         cudaFuncAttributeMaxDynamicSharedMemorySize,
                         SMEM_GEMM_BYTES);

    convert_kernel<<<((N_NODES + NBIG) * DIM + 255) / 256, 256>>>(node_states, W);
    gating_kernel<<<POS_TAB, 256>>>(Wp, bp);                 // + zero hist
    hist_kernel<<<(TOTAL_EDGES + 255) / 256, 256>>>(edges);
    scan1_kernel<<<N_SBLK, SCAN_BLK>>>();
    scan2_kernel<<<1, 128>>>();
    scan3_kernel<<<N_SBLK, SCAN_BLK>>>();
    place_kernel<<<(TOTAL_EDGES + 255) / 256, 256>>>(edges, posl);

    dim3 gg(NBIG / 128, N_PAD / 128);
    gemm_kernel<<<gg, 256, SMEM_GEMM_BYTES>>>(b);

    message_kernel<<<(N_NODES * 32 + 255) / 256, 256>>>(out);
}

// round 14
// speedup vs baseline: 2.3565x; 1.0538x over previous
#include <cuda_runtime.h>
#include <cuda_fp16.h>
#include <cstdint>
#include <cstddef>

#define N_NODES     100000
#define N_PAD       100096            /* 782 * 128 */
#define DIM         256
#define N_ET        6
#define M_PER_TYPE  400000
#define TOTAL_EDGES (N_ET * M_PER_TYPE)
#define NBIG        (N_ET * DIM)      /* 1536 */
#define POS_TAB     512
#define SCAN_BLK    1024
#define N_SBLK      ((N_NODES + SCAN_BLK - 1) / SCAN_BLK)   /* 98 */
#define CNT_PAD     (N_SBLK * SCAN_BLK)

// ---------------- device scratch (sanctioned: __device__ globals) ----------
__device__ __half   g_proph[(size_t)N_NODES * NBIG]; // 307.2 MB
__device__ __half   g_gatingh[POS_TAB * DIM];        // 256 KB (fp16 gating)
__device__ int      g_cnt[CNT_PAD];
__device__ int      g_off[N_NODES + 1];
__device__ int      g_cur[N_NODES];
__device__ int      g_bsum[N_SBLK + 1];
__device__ uint32_t g_sorted[TOTAL_EDGES];
__device__ __half   g_Ah[(size_t)N_PAD * DIM];       // 51.2 MB (pad rows stay 0)
__device__ __half   g_Wh[NBIG * DIM];                // 768 KB

// ---------------- fused fp16 convert pass ------------------------------------
__global__ void convert_kernel(const float* __restrict__ A,
                               const float* __restrict__ W) {
    int i = blockIdx.x * blockDim.x + threadIdx.x;
    const int nA = N_NODES * DIM;
    if (i < nA) {
        g_Ah[i] = __float2half_rn(A[i]);
    } else {
        int j = i - nA;
        if (j < NBIG * DIM) g_Wh[j] = __float2half_rn(W[j]);
    }
}

// ---------------- gating + zero counters ------------------------------------
__global__ void gating_kernel(const float* __restrict__ Wp,
                              const float* __restrict__ bp) {
    __shared__ float emb[DIM];
    const int p = blockIdx.x;
    const int t = threadIdx.x;
    if (t < 127) {
        float y    = (float)(2 * t) / 254.0f;
        float invf = 1.0f / powf(10000.0f, y);
        float ang  = (float)p * invf;
        emb[t]       = sinf(ang);
        emb[t + 127] = cosf(ang);
    } else if (t >= 254) {
        emb[t] = 0.0f;
    }
    int bi = blockIdx.x * blockDim.x + t;
    if (bi < CNT_PAD) g_cnt[bi] = 0;
    __syncthreads();

    float s = bp[t];
    const float* w = Wp + (size_t)t * DIM;
#pragma unroll 8
    for (int k = 0; k < DIM; ++k) s += emb[k] * w[k];
    g_gatingh[p * DIM + t] = __float2half_rn(2.0f / (1.0f + expf(-s)));
}

// ---------------- counting sort ---------------------------------------------
__global__ void hist_kernel(const int* __restrict__ edges) {
    int e = blockIdx.x * blockDim.x + threadIdx.x;
    if (e >= TOTAL_EDGES) return;
    atomicAdd(&g_cnt[edges[(size_t)2 * e + 1]], 1);
}

__global__ void scan1_kernel() {
    __shared__ int sh[SCAN_BLK];
    int t   = threadIdx.x;
    int idx = blockIdx.x * SCAN_BLK + t;
    int v   = (idx < N_NODES) ? g_cnt[idx] : 0;
    sh[t] = v;
    __syncthreads();
#pragma unroll
    for (int off = 1; off < SCAN_BLK; off <<= 1) {
        int x = (t >= off) ? sh[t - off] : 0;
        __syncthreads();
        sh[t] += x;
        __syncthreads();
    }
    if (idx < N_NODES) g_off[idx] = sh[t] - v;
    if (t == SCAN_BLK - 1) g_bsum[blockIdx.x] = sh[t];
}

__global__ void scan2_kernel() {
    __shared__ int sh[128];
    int t = threadIdx.x;
    int v = (t < N_SBLK) ? g_bsum[t] : 0;
    sh[t] = v;
    __syncthreads();
#pragma unroll
    for (int off = 1; off < 128; off <<= 1) {
        int x = (t >= off) ? sh[t - off] : 0;
        __syncthreads();
        sh[t] += x;
        __syncthreads();
    }
    if (t < N_SBLK) g_bsum[t] = sh[t] - v;
    if (t == 127) g_off[N_NODES] = sh[127];
}

__global__ void scan3_kernel() {
    int idx = blockIdx.x * SCAN_BLK + threadIdx.x;
    if (idx >= N_NODES) return;
    int o = g_off[idx] + g_bsum[blockIdx.x];
    g_off[idx] = o;
    g_cur[idx] = o;
}

__global__ void place_kernel(const int* __restrict__ edges,
                             const int* __restrict__ posl) {
    int e = blockIdx.x * blockDim.x + threadIdx.x;
    if (e >= TOTAL_EDGES) return;
    int src  = edges[(size_t)2 * e];
    int tgt  = edges[(size_t)2 * e + 1];
    int pos  = posl[e];
    int type = e / M_PER_TYPE;
    int p = atomicAdd(&g_cur[tgt], 1);
    g_sorted[p] = ((uint32_t)src << 12) | ((uint32_t)type << 9) | (uint32_t)pos;
}

// ---------------- GEMM: fp16 mma, 128x128 tile, cp.async double-buffered ----
#define OFF_AH 0
#define OFF_BH 5120
#define BUF_HALVES 10240
#define SMEM_GEMM_BYTES (2 * BUF_HALVES * 2)   /* 40960 */

__device__ __forceinline__ uint32_t smem_u32(const void* p) {
    uint32_t a;
    asm("{ .reg .u64 t; cvta.to.shared.u64 t, %1; cvt.u32.u64 %0, t; }"
        : "=r"(a) : "l"(p));
    return a;
}
__device__ __forceinline__ void cp16(uint32_t dst, const void* src) {
    asm volatile("cp.async.ca.shared.global [%0], [%1], 16;"
                 :: "r"(dst), "l"(src));
}
__device__ __forceinline__ void cp_commit() {
    asm volatile("cp.async.commit_group;" ::: "memory");
}
template <int N>
__device__ __forceinline__ void cp_wait() {
    asm volatile("cp.async.wait_group %0;" :: "n"(N) : "memory");
}
__device__ __forceinline__ void mmah16(float* d, const uint32_t* a, const uint32_t* b) {
    asm volatile(
        "mma.sync.aligned.m16n8k16.row.col.f32.f16.f16.f32 "
        "{%0,%1,%2,%3}, {%4,%5,%6,%7}, {%8,%9}, {%0,%1,%2,%3};"
        : "+f"(d[0]), "+f"(d[1]), "+f"(d[2]), "+f"(d[3])
        : "r"(a[0]), "r"(a[1]), "r"(a[2]), "r"(a[3]), "r"(b[0]), "r"(b[1]));
}

__global__ __launch_bounds__(256, 2)
void gemm_kernel(const float* __restrict__ bias) {
    extern __shared__ __half sm[];
    const uint32_t sb = smem_u32(sm);
    const int tid  = threadIdx.x;
    const int lane = tid & 31;
    const int wid  = tid >> 5;
    const int wm   = (wid & 3) * 32;
    const int wn   = (wid >> 2) * 64;
    const int mBase = blockIdx.y * 128;    // < N_PAD, pad rows are zero
    const int nBase = blockIdx.x * 128;

    auto stage = [&](int buf, int kc) {
        uint32_t base = sb + buf * (BUF_HALVES * 2);
#pragma unroll
        for (int t4 = 0; t4 < 4; t4++) {
            int t = tid + t4 * 256;
            if (t < 512) {
                int r = t >> 2, c = t & 3;
                cp16(base + (OFF_AH + r * 40) * 2 + c * 16,
                     g_Ah + (size_t)(mBase + r) * DIM + kc * 32 + c * 8);
            } else {
                int i = t - 512, r = i >> 2, c = i & 3;
                cp16(base + (OFF_BH + r * 40) * 2 + c * 16,
                     g_Wh + (size_t)(nBase + r) * DIM + kc * 32 + c * 8);
            }
        }
    };

    float acc[2][8][4];
#pragma unroll
    for (int i = 0; i < 2; i++)
#pragma unroll
        for (int j = 0; j < 8; j++)
#pragma unroll
            for (int k = 0; k < 4; k++) acc[i][j][k] = 0.f;

    stage(0, 0);
    cp_commit();

    int buf = 0;
    for (int kc = 0; kc < 8; kc++) {
        if (kc < 7) {
            stage(buf ^ 1, kc + 1);
            cp_commit();
            cp_wait<1>();
        } else {
            cp_wait<0>();
        }
        __syncthreads();

        const __half* Abh = sm + buf * BUF_HALVES + OFF_AH;
        const __half* Bbh = sm + buf * BUF_HALVES + OFF_BH;

#pragma unroll
        for (int kk = 0; kk < 32; kk += 16) {
            const int cA = kk + (lane & 3) * 2;
            uint32_t ah[2][4];
#pragma unroll
            for (int mt = 0; mt < 2; mt++) {
                const __half* r0 = Abh + (wm + mt * 16 + (lane >> 2)) * 40;
                ah[mt][0] = *reinterpret_cast<const uint32_t*>(r0 + cA);
                ah[mt][1] = *reinterpret_cast<const uint32_t*>(r0 + 8 * 40 + cA);
                ah[mt][2] = *reinterpret_cast<const uint32_t*>(r0 + cA + 8);
                ah[mt][3] = *reinterpret_cast<const uint32_t*>(r0 + 8 * 40 + cA + 8);
            }
            uint32_t bh[8][2];
#pragma unroll
            for (int nt = 0; nt < 8; nt++) {
                const __half* n0 = Bbh + (wn + nt * 8 + (lane >> 2)) * 40;
                bh[nt][0] = *reinterpret_cast<const uint32_t*>(n0 + cA);
                bh[nt][1] = *reinterpret_cast<const uint32_t*>(n0 + cA + 8);
            }
#pragma unroll
            for (int mt = 0; mt < 2; mt++)
#pragma unroll
                for (int nt = 0; nt < 8; nt++)
                    mmah16(acc[mt][nt], ah[mt], bh[nt]);
        }
        __syncthreads();
        buf ^= 1;
    }

#pragma unroll
    for (int mt = 0; mt < 2; mt++) {
#pragma unroll
        for (int nt = 0; nt < 8; nt++) {
            int row = mBase + wm + mt * 16 + (lane >> 2);
            int col = nBase + wn + nt * 8 + 2 * (lane & 3);
            float b0 = bias[col], b1 = bias[col + 1];
            if (row < N_NODES) {
                __half2 h = __floats2half2_rn(acc[mt][nt][0] + b0, acc[mt][nt][1] + b1);
                *reinterpret_cast<__half2*>(&g_proph[(size_t)row * NBIG + col]) = h;
            }
            if (row + 8 < N_NODES) {
                __half2 h = __floats2half2_rn(acc[mt][nt][2] + b0, acc[mt][nt][3] + b1);
                *reinterpret_cast<__half2*>(&g_proph[(size_t)(row + 8) * NBIG + col]) = h;
            }
        }
    }
}

// ---------------- message: warp per target, fp16 prop + fp16 gating ---------
__device__ __forceinline__ void acc_rec(uint4 v, uint4 g, float4& a0, float4& a1) {
    float2 f, gg;
    f  = __half22float2(*reinterpret_cast<__half2*>(&v.x));
    gg = __half22float2(*reinterpret_cast<__half2*>(&g.x));
    a0.x += f.x * gg.x; a0.y += f.y * gg.y;
    f  = __half22float2(*reinterpret_cast<__half2*>(&v.y));
    gg = __half22float2(*reinterpret_cast<__half2*>(&g.y));
    a0.z += f.x * gg.x; a0.w += f.y * gg.y;
    f  = __half22float2(*reinterpret_cast<__half2*>(&v.z));
    gg = __half22float2(*reinterpret_cast<__half2*>(&g.z));
    a1.x += f.x * gg.x; a1.y += f.y * gg.y;
    f  = __half22float2(*reinterpret_cast<__half2*>(&v.w));
    gg = __half22float2(*reinterpret_cast<__half2*>(&g.w));
    a1.z += f.x * gg.x; a1.w += f.y * gg.y;
}

__global__ __launch_bounds__(256)
void message_kernel(float* __restrict__ out) {
    int t    = (blockIdx.x * blockDim.x + threadIdx.x) >> 5;
    int lane = threadIdx.x & 31;
    if (t >= N_NODES) return;

    const int s0 = g_off[t];
    const int s1 = g_off[t + 1];

    float4 a0 = make_float4(0.f, 0.f, 0.f, 0.f);
    float4 a1 = make_float4(0.f, 0.f, 0.f, 0.f);

    int e = s0;
    for (; e + 3 < s1; e += 4) {
        uint32_t c0 = g_sorted[e],     c1 = g_sorted[e + 1];
        uint32_t c2 = g_sorted[e + 2], c3 = g_sorted[e + 3];

        const uint4* p0 = reinterpret_cast<const uint4*>(
            g_proph + (size_t)(c0 >> 12) * NBIG + ((c0 >> 9) & 7) * DIM) + lane;
        const uint4* p1 = reinterpret_cast<const uint4*>(
            g_proph + (size_t)(c1 >> 12) * NBIG + ((c1 >> 9) & 7) * DIM) + lane;
        const uint4* p2 = reinterpret_cast<const uint4*>(
            g_proph + (size_t)(c2 >> 12) * NBIG + ((c2 >> 9) & 7) * DIM) + lane;
        const uint4* p3 = reinterpret_cast<const uint4*>(
            g_proph + (size_t)(c3 >> 12) * NBIG + ((c3 >> 9) & 7) * DIM) + lane;
        uint4 v0 = __ldg(p0);
        uint4 v1 = __ldg(p1);
        uint4 v2 = __ldg(p2);
        uint4 v3 = __ldg(p3);

        const uint4* ga = reinterpret_cast<const uint4*>(
            g_gatingh + (size_t)(c0 & 511) * DIM) + lane;
        const uint4* gb = reinterpret_cast<const uint4*>(
            g_gatingh + (size_t)(c1 & 511) * DIM) + lane;
        const uint4* gc = reinterpret_cast<const uint4*>(
            g_gatingh + (size_t)(c2 & 511) * DIM) + lane;
        const uint4* gd = reinterpret_cast<const uint4*>(
            g_gatingh + (size_t)(c3 & 511) * DIM) + lane;
        uint4 gv0 = __ldg(ga);
        uint4 gv1 = __ldg(gb);
        uint4 gv2 = __ldg(gc);
        uint4 gv3 = __ldg(gd);

        acc_rec(v0, gv0, a0, a1);
        acc_rec(v1, gv1, a0, a1);
        acc_rec(v2, gv2, a0, a1);
        acc_rec(v3, gv3, a0, a1);
    }
    for (; e < s1; ++e) {
        uint32_t c0 = g_sorted[e];
        const uint4* p0 = reinterpret_cast<const uint4*>(
            g_proph + (size_t)(c0 >> 12) * NBIG + ((c0 >> 9) & 7) * DIM) + lane;
        uint4 v0 = __ldg(p0);
        const uint4* ga = reinterpret_cast<const uint4*>(
            g_gatingh + (size_t)(c0 & 511) * DIM) + lane;
        uint4 gv0 = __ldg(ga);
        acc_rec(v0, gv0, a0, a1);
    }

    int deg = s1 - s0;
    float div = ((deg == 0) ? 1.0f : (float)deg) + 1e-8f;
    float s = 1.0f / div;
    a0.x *= s; a0.y *= s; a0.z *= s; a0.w *= s;
    a1.x *= s; a1.y *= s; a1.z *= s; a1.w *= s;

    float4* dst = reinterpret_cast<float4*>(out + (size_t)t * DIM) + lane * 2;
    dst[0] = a0;
    dst[1] = a1;
}

// ---------------- launch: two-stream fork/join (capture-legal) ---------------
extern "C" void kernel_launch(void* const* d_in, const int* in_sizes, int n_in,
                              void* d_out, int out_size) {
    const float* node_states = (const float*)d_in[0];
    const float* W    = (const float*)d_in[1];
    const float* b    = (const float*)d_in[2];
    const float* Wp   = (const float*)d_in[3];
    const float* bp   = (const float*)d_in[4];
    const int*   edges = (const int*)d_in[5];
    const int*   posl  = (const int*)d_in[6];
    float* out = (float*)d_out;

    static cudaStream_t sB = nullptr;
    static cudaEvent_t  evFork = nullptr, evJoin = nullptr;
    if (!sB) {
        cudaStreamCreateWithFlags(&sB, cudaStreamNonBlocking);
        cudaEventCreateWithFlags(&evFork, cudaEventDisableTiming);
        cudaEventCreateWithFlags(&evJoin, cudaEventDisableTiming);
        cudaFuncSetAttribute(gemm_kernel,
                             cudaFuncAttributeMaxDynamicSharedMemorySize,
                             SMEM_GEMM_BYTES);
    }

    // fork: chain B (gating + sort prep) runs concurrently with chain A
    cudaEventRecord(evFork, 0);
    cudaStreamWaitEvent(sB, evFork, 0);

    // chain B (stream sB): gating (+zero hist) -> hist -> scan -> place
    gating_kernel<<<POS_TAB, 256, 0, sB>>>(Wp, bp);
    hist_kernel<<<(TOTAL_EDGES + 255) / 256, 256, 0, sB>>>(edges);
    scan1_kernel<<<N_SBLK, SCAN_BLK, 0, sB>>>();
    scan2_kernel<<<1, 128, 0, sB>>>();
    scan3_kernel<<<N_SBLK, SCAN_BLK, 0, sB>>>();
    place_kernel<<<(TOTAL_EDGES + 255) / 256, 256, 0, sB>>>(edges, posl);
    cudaEventRecord(evJoin, sB);

    // chain A (default stream): convert -> gemm
    convert_kernel<<<((N_NODES + NBIG) * DIM + 255) / 256, 256>>>(node_states, W);
    dim3 gg(NBIG / 128, N_PAD / 128);
    gemm_kernel<<<gg, 256, SMEM_GEMM_BYTES>>>(b);

    // join, then message
    cudaStreamWaitEvent(0, evJoin, 0);
    message_kernel<<<(N_NODES * 32 + 255) / 256, 256>>>(out);
}

// round 15
// speedup vs baseline: 2.5300x; 1.0736x over previous
#include <cuda_runtime.h>
#include <cuda_fp16.h>
#include <cstdint>
#include <cstddef>

#define N_NODES     100000
#define N_PAD       100096            /* 782 * 128 */
#define DIM         256
#define N_ET        6
#define M_PER_TYPE  400000
#define TOTAL_EDGES (N_ET * M_PER_TYPE)
#define NBIG        (N_ET * DIM)      /* 1536 */
#define POS_TAB     512
#define SCAN_BLK    1024
#define N_SBLK      ((N_NODES + SCAN_BLK - 1) / SCAN_BLK)   /* 98 */
#define CNT_PAD     (N_SBLK * SCAN_BLK)

// ---------------- device scratch (sanctioned: __device__ globals) ----------
__device__ __half   g_proph[(size_t)N_NODES * NBIG]; // 307.2 MB
__device__ __half   g_gatingh[POS_TAB * DIM];        // 256 KB (fp16 gating)
__device__ int      g_cnt[CNT_PAD];
__device__ int      g_off[N_NODES + 1];
__device__ int      g_cur[N_NODES];
__device__ int      g_bsum[N_SBLK + 1];
__device__ uint32_t g_sorted[TOTAL_EDGES];
__device__ __half   g_Ah[(size_t)N_PAD * DIM];       // 51.2 MB (pad rows stay 0)
__device__ __half   g_Wh[NBIG * DIM];                // 768 KB

// ---------------- fused fp16 convert pass ------------------------------------
__global__ void convert_kernel(const float* __restrict__ A,
                               const float* __restrict__ W) {
    int i = blockIdx.x * blockDim.x + threadIdx.x;
    const int nA = N_NODES * DIM;
    if (i < nA) {
        g_Ah[i] = __float2half_rn(A[i]);
    } else {
        int j = i - nA;
        if (j < NBIG * DIM) g_Wh[j] = __float2half_rn(W[j]);
    }
}

// ---------------- gating + zero counters ------------------------------------
__global__ void gating_kernel(const float* __restrict__ Wp,
                              const float* __restrict__ bp) {
    __shared__ float emb[DIM];
    const int p = blockIdx.x;
    const int t = threadIdx.x;
    if (t < 127) {
        float y    = (float)(2 * t) / 254.0f;
        float invf = 1.0f / powf(10000.0f, y);
        float ang  = (float)p * invf;
        emb[t]       = sinf(ang);
        emb[t + 127] = cosf(ang);
    } else if (t >= 254) {
        emb[t] = 0.0f;
    }
    int bi = blockIdx.x * blockDim.x + t;
    if (bi < CNT_PAD) g_cnt[bi] = 0;
    __syncthreads();

    float s = bp[t];
    const float* w = Wp + (size_t)t * DIM;
#pragma unroll 8
    for (int k = 0; k < DIM; ++k) s += emb[k] * w[k];
    g_gatingh[p * DIM + t] = __float2half_rn(2.0f / (1.0f + expf(-s)));
}

// ---------------- counting sort ---------------------------------------------
__global__ void hist_kernel(const int* __restrict__ edges) {
    int e = blockIdx.x * blockDim.x + threadIdx.x;
    if (e >= TOTAL_EDGES) return;
    atomicAdd(&g_cnt[edges[(size_t)2 * e + 1]], 1);
}

__global__ void scan1_kernel() {
    __shared__ int sh[SCAN_BLK];
    int t   = threadIdx.x;
    int idx = blockIdx.x * SCAN_BLK + t;
    int v   = (idx < N_NODES) ? g_cnt[idx] : 0;
    sh[t] = v;
    __syncthreads();
#pragma unroll
    for (int off = 1; off < SCAN_BLK; off <<= 1) {
        int x = (t >= off) ? sh[t - off] : 0;
        __syncthreads();
        sh[t] += x;
        __syncthreads();
    }
    if (idx < N_NODES) g_off[idx] = sh[t] - v;
    if (t == SCAN_BLK - 1) g_bsum[blockIdx.x] = sh[t];
}

__global__ void scan2_kernel() {
    __shared__ int sh[128];
    int t = threadIdx.x;
    int v = (t < N_SBLK) ? g_bsum[t] : 0;
    sh[t] = v;
    __syncthreads();
#pragma unroll
    for (int off = 1; off < 128; off <<= 1) {
        int x = (t >= off) ? sh[t - off] : 0;
        __syncthreads();
        sh[t] += x;
        __syncthreads();
    }
    if (t < N_SBLK) g_bsum[t] = sh[t] - v;
    if (t == 127) g_off[N_NODES] = sh[127];
}

__global__ void scan3_kernel() {
    int idx = blockIdx.x * SCAN_BLK + threadIdx.x;
    if (idx >= N_NODES) return;
    int o = g_off[idx] + g_bsum[blockIdx.x];
    g_off[idx] = o;
    g_cur[idx] = o;
}

__global__ void place_kernel(const int* __restrict__ edges,
                             const int* __restrict__ posl) {
    int e = blockIdx.x * blockDim.x + threadIdx.x;
    if (e >= TOTAL_EDGES) return;
    int src  = edges[(size_t)2 * e];
    int tgt  = edges[(size_t)2 * e + 1];
    int pos  = posl[e];
    int type = e / M_PER_TYPE;
    int p = atomicAdd(&g_cur[tgt], 1);
    g_sorted[p] = ((uint32_t)src << 12) | ((uint32_t)type << 9) | (uint32_t)pos;
}

// ---------------- GEMM: fp16 mma + ldmatrix, cp.async double-buffered -------
#define OFF_AH 0
#define OFF_BH 5120
#define BUF_HALVES 10240
#define SMEM_GEMM_BYTES (2 * BUF_HALVES * 2)   /* 40960 */

__device__ __forceinline__ uint32_t smem_u32(const void* p) {
    uint32_t a;
    asm("{ .reg .u64 t; cvta.to.shared.u64 t, %1; cvt.u32.u64 %0, t; }"
        : "=r"(a) : "l"(p));
    return a;
}
__device__ __forceinline__ void cp16(uint32_t dst, const void* src) {
    asm volatile("cp.async.ca.shared.global [%0], [%1], 16;"
                 :: "r"(dst), "l"(src));
}
__device__ __forceinline__ void cp_commit() {
    asm volatile("cp.async.commit_group;" ::: "memory");
}
template <int N>
__device__ __forceinline__ void cp_wait() {
    asm volatile("cp.async.wait_group %0;" :: "n"(N) : "memory");
}
__device__ __forceinline__ void ldsm4(uint32_t& r0, uint32_t& r1,
                                      uint32_t& r2, uint32_t& r3, uint32_t addr) {
    asm volatile("ldmatrix.sync.aligned.m8n8.x4.shared.b16 {%0,%1,%2,%3}, [%4];"
                 : "=r"(r0), "=r"(r1), "=r"(r2), "=r"(r3) : "r"(addr));
}
__device__ __forceinline__ void mmah16(float* d, const uint32_t* a, const uint32_t* b) {
    asm volatile(
        "mma.sync.aligned.m16n8k16.row.col.f32.f16.f16.f32 "
        "{%0,%1,%2,%3}, {%4,%5,%6,%7}, {%8,%9}, {%0,%1,%2,%3};"
        : "+f"(d[0]), "+f"(d[1]), "+f"(d[2]), "+f"(d[3])
        : "r"(a[0]), "r"(a[1]), "r"(a[2]), "r"(a[3]), "r"(b[0]), "r"(b[1]));
}

__global__ __launch_bounds__(256, 2)
void gemm_kernel(const float* __restrict__ bias) {
    extern __shared__ __half sm[];
    const uint32_t sb = smem_u32(sm);
    const int tid  = threadIdx.x;
    const int lane = tid & 31;
    const int wid  = tid >> 5;
    const int wm   = (wid & 3) * 32;
    const int wn   = (wid >> 2) * 64;
    const int mBase = blockIdx.y * 128;    // < N_PAD, pad rows are zero
    const int nBase = blockIdx.x * 128;

    // ldmatrix lane decomposition: g = matrix id (0..3), i = row within matrix
    const int g = lane >> 3;
    const int i = lane & 7;
    const int a_row_off = (wm + i + ((g & 1) << 3)) * 40 + ((g >> 1) << 3);
    const int b_col_off = ((g & 1) << 3);
    const int b_row_i   = wn + ((g >> 1) << 3) + i;   // + pair*16 later

    auto stage = [&](int buf, int kc) {
        uint32_t base = sb + buf * (BUF_HALVES * 2);
#pragma unroll
        for (int t4 = 0; t4 < 4; t4++) {
            int t = tid + t4 * 256;
            if (t < 512) {
                int r = t >> 2, c = t & 3;
                cp16(base + (OFF_AH + r * 40) * 2 + c * 16,
                     g_Ah + (size_t)(mBase + r) * DIM + kc * 32 + c * 8);
            } else {
                int idx = t - 512, r = idx >> 2, c = idx & 3;
                cp16(base + (OFF_BH + r * 40) * 2 + c * 16,
                     g_Wh + (size_t)(nBase + r) * DIM + kc * 32 + c * 8);
            }
        }
    };

    float acc[2][8][4];
#pragma unroll
    for (int x = 0; x < 2; x++)
#pragma unroll
        for (int j = 0; j < 8; j++)
#pragma unroll
            for (int k = 0; k < 4; k++) acc[x][j][k] = 0.f;

    stage(0, 0);
    cp_commit();

    int buf = 0;
    for (int kc = 0; kc < 8; kc++) {
        if (kc < 7) {
            stage(buf ^ 1, kc + 1);
            cp_commit();
            cp_wait<1>();
        } else {
            cp_wait<0>();
        }
        __syncthreads();

        const uint32_t base = sb + buf * (BUF_HALVES * 2);

#pragma unroll
        for (int kk = 0; kk < 32; kk += 16) {
            uint32_t ah[2][4];
#pragma unroll
            for (int mt = 0; mt < 2; mt++) {
                uint32_t addr = base + (OFF_AH + a_row_off + mt * 16 * 40 + kk) * 2;
                ldsm4(ah[mt][0], ah[mt][1], ah[mt][2], ah[mt][3], addr);
            }
            uint32_t bh[8][2];
#pragma unroll
            for (int p = 0; p < 4; p++) {
                uint32_t addr = base + (OFF_BH + (b_row_i + p * 16) * 40 + kk + b_col_off) * 2;
                ldsm4(bh[2 * p][0], bh[2 * p][1], bh[2 * p + 1][0], bh[2 * p + 1][1], addr);
            }
#pragma unroll
            for (int mt = 0; mt < 2; mt++)
#pragma unroll
                for (int nt = 0; nt < 8; nt++)
                    mmah16(acc[mt][nt], ah[mt], bh[nt]);
        }
        __syncthreads();
        buf ^= 1;
    }

#pragma unroll
    for (int mt = 0; mt < 2; mt++) {
#pragma unroll
        for (int nt = 0; nt < 8; nt++) {
            int row = mBase + wm + mt * 16 + (lane >> 2);
            int col = nBase + wn + nt * 8 + 2 * (lane & 3);
            float b0 = bias[col], b1 = bias[col + 1];
            if (row < N_NODES) {
                __half2 h = __floats2half2_rn(acc[mt][nt][0] + b0, acc[mt][nt][1] + b1);
                *reinterpret_cast<__half2*>(&g_proph[(size_t)row * NBIG + col]) = h;
            }
            if (row + 8 < N_NODES) {
                __half2 h = __floats2half2_rn(acc[mt][nt][2] + b0, acc[mt][nt][3] + b1);
                *reinterpret_cast<__half2*>(&g_proph[(size_t)(row + 8) * NBIG + col]) = h;
            }
        }
    }
}

// ---------------- message: warp per target, fp16 prop + fp16 gating ---------
__device__ __forceinline__ void acc_rec(uint4 v, uint4 g, float4& a0, float4& a1) {
    float2 f, gg;
    f  = __half22float2(*reinterpret_cast<__half2*>(&v.x));
    gg = __half22float2(*reinterpret_cast<__half2*>(&g.x));
    a0.x += f.x * gg.x; a0.y += f.y * gg.y;
    f  = __half22float2(*reinterpret_cast<__half2*>(&v.y));
    gg = __half22float2(*reinterpret_cast<__half2*>(&g.y));
    a0.z += f.x * gg.x; a0.w += f.y * gg.y;
    f  = __half22float2(*reinterpret_cast<__half2*>(&v.z));
    gg = __half22float2(*reinterpret_cast<__half2*>(&g.z));
    a1.x += f.x * gg.x; a1.y += f.y * gg.y;
    f  = __half22float2(*reinterpret_cast<__half2*>(&v.w));
    gg = __half22float2(*reinterpret_cast<__half2*>(&g.w));
    a1.z += f.x * gg.x; a1.w += f.y * gg.y;
}

__global__ __launch_bounds__(256)
void message_kernel(float* __restrict__ out) {
    int t    = (blockIdx.x * blockDim.x + threadIdx.x) >> 5;
    int lane = threadIdx.x & 31;
    if (t >= N_NODES) return;

    const int s0 = g_off[t];
    const int s1 = g_off[t + 1];

    float4 a0 = make_float4(0.f, 0.f, 0.f, 0.f);
    float4 a1 = make_float4(0.f, 0.f, 0.f, 0.f);

    int e = s0;
    for (; e + 3 < s1; e += 4) {
        uint32_t c0 = g_sorted[e],     c1 = g_sorted[e + 1];
        uint32_t c2 = g_sorted[e + 2], c3 = g_sorted[e + 3];

        const uint4* p0 = reinterpret_cast<const uint4*>(
            g_proph + (size_t)(c0 >> 12) * NBIG + ((c0 >> 9) & 7) * DIM) + lane;
        const uint4* p1 = reinterpret_cast<const uint4*>(
            g_proph + (size_t)(c1 >> 12) * NBIG + ((c1 >> 9) & 7) * DIM) + lane;
        const uint4* p2 = reinterpret_cast<const uint4*>(
            g_proph + (size_t)(c2 >> 12) * NBIG + ((c2 >> 9) & 7) * DIM) + lane;
        const uint4* p3 = reinterpret_cast<const uint4*>(
            g_proph + (size_t)(c3 >> 12) * NBIG + ((c3 >> 9) & 7) * DIM) + lane;
        uint4 v0 = __ldg(p0);
        uint4 v1 = __ldg(p1);
        uint4 v2 = __ldg(p2);
        uint4 v3 = __ldg(p3);

        const uint4* ga = reinterpret_cast<const uint4*>(
            g_gatingh + (size_t)(c0 & 511) * DIM) + lane;
        const uint4* gb = reinterpret_cast<const uint4*>(
            g_gatingh + (size_t)(c1 & 511) * DIM) + lane;
        const uint4* gc = reinterpret_cast<const uint4*>(
            g_gatingh + (size_t)(c2 & 511) * DIM) + lane;
        const uint4* gd = reinterpret_cast<const uint4*>(
            g_gatingh + (size_t)(c3 & 511) * DIM) + lane;
        uint4 gv0 = __ldg(ga);
        uint4 gv1 = __ldg(gb);
        uint4 gv2 = __ldg(gc);
        uint4 gv3 = __ldg(gd);

        acc_rec(v0, gv0, a0, a1);
        acc_rec(v1, gv1, a0, a1);
        acc_rec(v2, gv2, a0, a1);
        acc_rec(v3, gv3, a0, a1);
    }
    for (; e < s1; ++e) {
        uint32_t c0 = g_sorted[e];
        const uint4* p0 = reinterpret_cast<const uint4*>(
            g_proph + (size_t)(c0 >> 12) * NBIG + ((c0 >> 9) & 7) * DIM) + lane;
        uint4 v0 = __ldg(p0);
        const uint4* ga = reinterpret_cast<const uint4*>(
            g_gatingh + (size_t)(c0 & 511) * DIM) + lane;
        uint4 gv0 = __ldg(ga);
        acc_rec(v0, gv0, a0, a1);
    }

    int deg = s1 - s0;
    float div = ((deg == 0) ? 1.0f : (float)deg) + 1e-8f;
    float s = 1.0f / div;
    a0.x *= s; a0.y *= s; a0.z *= s; a0.w *= s;
    a1.x *= s; a1.y *= s; a1.z *= s; a1.w *= s;

    float4* dst = reinterpret_cast<float4*>(out + (size_t)t * DIM) + lane * 2;
    dst[0] = a0;
    dst[1] = a1;
}

// ---------------- launch: two-stream fork/join (capture-legal) ---------------
extern "C" void kernel_launch(void* const* d_in, const int* in_sizes, int n_in,
                              void* d_out, int out_size) {
    const float* node_states = (const float*)d_in[0];
    const float* W    = (const float*)d_in[1];
    const float* b    = (const float*)d_in[2];
    const float* Wp   = (const float*)d_in[3];
    const float* bp   = (const float*)d_in[4];
    const int*   edges = (const int*)d_in[5];
    const int*   posl  = (const int*)d_in[6];
    float* out = (float*)d_out;

    static cudaStream_t sB = nullptr;
    static cudaEvent_t  evFork = nullptr, evJoin = nullptr;
    if (!sB) {
        cudaStreamCreateWithFlags(&sB, cudaStreamNonBlocking);
        cudaEventCreateWithFlags(&evFork, cudaEventDisableTiming);
        cudaEventCreateWithFlags(&evJoin, cudaEventDisableTiming);
        cudaFuncSetAttribute(gemm_kernel,
                             cudaFuncAttributeMaxDynamicSharedMemorySize,
                             SMEM_GEMM_BYTES);
    }

    cudaEventRecord(evFork, 0);
    cudaStreamWaitEvent(sB, evFork, 0);

    // chain B (stream sB): gating (+zero hist) -> hist -> scan -> place
    gating_kernel<<<POS_TAB, 256, 0, sB>>>(Wp, bp);
    hist_kernel<<<(TOTAL_EDGES + 255) / 256, 256, 0, sB>>>(edges);
    scan1_kernel<<<N_SBLK, SCAN_BLK, 0, sB>>>();
    scan2_kernel<<<1, 128, 0, sB>>>();
    scan3_kernel<<<N_SBLK, SCAN_BLK, 0, sB>>>();
    place_kernel<<<(TOTAL_EDGES + 255) / 256, 256, 0, sB>>>(edges, posl);
    cudaEventRecord(evJoin, sB);

    // chain A (default stream): convert -> gemm
    convert_kernel<<<((N_NODES + NBIG) * DIM + 255) / 256, 256>>>(node_states, W);
    dim3 gg(NBIG / 128, N_PAD / 128);
    gemm_kernel<<<gg, 256, SMEM_GEMM_BYTES>>>(b);

    cudaStreamWaitEvent(0, evJoin, 0);
    message_kernel<<<(N_NODES * 32 + 255) / 256, 256>>>(out);
}

// round 16
// speedup vs baseline: 2.5975x; 1.0267x over previous
#include <cuda_runtime.h>
#include <cuda_fp16.h>
#include <cstdint>
#include <cstddef>

#define N_NODES     100000
#define N_PAD       100096            /* 782 * 128 */
#define DIM         256
#define N_ET        6
#define M_PER_TYPE  400000
#define TOTAL_EDGES (N_ET * M_PER_TYPE)
#define PAD_EDGES   (TOTAL_EDGES + 7 * N_NODES + 8)   /* padded-seg worst case */
#define NBIG        (N_ET * DIM)      /* 1536 */
#define POS_TAB     512
#define SCAN_BLK    1024
#define N_SBLK      ((N_NODES + SCAN_BLK - 1) / SCAN_BLK)   /* 98 */
#define CNT_PAD     (N_SBLK * SCAN_BLK)
#define DUMMY_REC   (((uint32_t)N_NODES) << 12)       /* zero prop row, pos 0 */

// ---------------- device scratch (sanctioned: __device__ globals) ----------
// +1 row on g_proph: the dummy row, never written -> stays zero (module init)
__device__ __half   g_proph[(size_t)(N_NODES + 1) * NBIG];
__device__ __half   g_gatingh[POS_TAB * DIM];
__device__ int      g_cnt[CNT_PAD];
__device__ int      g_off[N_NODES + 1];               // PADDED CSR offsets
__device__ int      g_cur[N_NODES];
__device__ int      g_bsum[N_SBLK + 1];
__device__ uint32_t g_sorted[PAD_EDGES];
__device__ __half   g_Ah[(size_t)N_PAD * DIM];
__device__ __half   g_Wh[NBIG * DIM];

// ---------------- fused fp16 convert pass ------------------------------------
__global__ void convert_kernel(const float* __restrict__ A,
                               const float* __restrict__ W) {
    int i = blockIdx.x * blockDim.x + threadIdx.x;
    const int nA = N_NODES * DIM;
    if (i < nA) {
        g_Ah[i] = __float2half_rn(A[i]);
    } else {
        int j = i - nA;
        if (j < NBIG * DIM) g_Wh[j] = __float2half_rn(W[j]);
    }
}

// ---------------- gating + zero counters ------------------------------------
__global__ void gating_kernel(const float* __restrict__ Wp,
                              const float* __restrict__ bp) {
    __shared__ float emb[DIM];
    const int p = blockIdx.x;
    const int t = threadIdx.x;
    if (t < 127) {
        float y    = (float)(2 * t) / 254.0f;
        float invf = 1.0f / powf(10000.0f, y);
        float ang  = (float)p * invf;
        emb[t]       = sinf(ang);
        emb[t + 127] = cosf(ang);
    } else if (t >= 254) {
        emb[t] = 0.0f;
    }
    int bi = blockIdx.x * blockDim.x + t;
    if (bi < CNT_PAD) g_cnt[bi] = 0;
    __syncthreads();

    float s = bp[t];
    const float* w = Wp + (size_t)t * DIM;
#pragma unroll 8
    for (int k = 0; k < DIM; ++k) s += emb[k] * w[k];
    g_gatingh[p * DIM + t] = __float2half_rn(2.0f / (1.0f + expf(-s)));
}

// ---------------- counting sort (padded-to-8 segments) -----------------------
__global__ void hist_kernel(const int* __restrict__ edges) {
    int e = blockIdx.x * blockDim.x + threadIdx.x;
    if (e >= TOTAL_EDGES) return;
    atomicAdd(&g_cnt[edges[(size_t)2 * e + 1]], 1);
}

__global__ void scan1_kernel() {
    __shared__ int sh[SCAN_BLK];
    int t   = threadIdx.x;
    int idx = blockIdx.x * SCAN_BLK + t;
    int v   = (idx < N_NODES) ? ((g_cnt[idx] + 7) & ~7) : 0;   // round8
    sh[t] = v;
    __syncthreads();
#pragma unroll
    for (int off = 1; off < SCAN_BLK; off <<= 1) {
        int x = (t >= off) ? sh[t - off] : 0;
        __syncthreads();
        sh[t] += x;
        __syncthreads();
    }
    if (idx < N_NODES) g_off[idx] = sh[t] - v;
    if (t == SCAN_BLK - 1) g_bsum[blockIdx.x] = sh[t];
}

__global__ void scan2_kernel() {
    __shared__ int sh[128];
    int t = threadIdx.x;
    int v = (t < N_SBLK) ? g_bsum[t] : 0;
    sh[t] = v;
    __syncthreads();
#pragma unroll
    for (int off = 1; off < 128; off <<= 1) {
        int x = (t >= off) ? sh[t - off] : 0;
        __syncthreads();
        sh[t] += x;
        __syncthreads();
    }
    if (t < N_SBLK) g_bsum[t] = sh[t] - v;
    if (t == 127) g_off[N_NODES] = sh[127];
}

__global__ void scan3_kernel() {
    int idx = blockIdx.x * SCAN_BLK + threadIdx.x;
    if (idx >= N_NODES) return;
    int o = g_off[idx] + g_bsum[blockIdx.x];
    g_off[idx] = o;
    g_cur[idx] = o;
}

__global__ void place_kernel(const int* __restrict__ edges,
                             const int* __restrict__ posl) {
    int e = blockIdx.x * blockDim.x + threadIdx.x;
    if (e >= TOTAL_EDGES) return;
    int src  = edges[(size_t)2 * e];
    int tgt  = edges[(size_t)2 * e + 1];
    int pos  = posl[e];
    int type = e / M_PER_TYPE;
    int p = atomicAdd(&g_cur[tgt], 1);
    g_sorted[p] = ((uint32_t)src << 12) | ((uint32_t)type << 9) | (uint32_t)pos;
}

// fill padded slots with the zero-row dummy record
__global__ void fill_kernel() {
    int t = blockIdx.x * blockDim.x + threadIdx.x;
    if (t >= N_NODES) return;
    int e   = g_cur[t];           // = seg start + true count (post-place)
    int end = g_off[t + 1];
    for (; e < end; ++e) g_sorted[e] = DUMMY_REC;
}

// ---------------- GEMM: fp16 mma + ldmatrix, cp.async double-buffered -------
#define OFF_AH 0
#define OFF_BH 5120
#define BUF_HALVES 10240
#define SMEM_GEMM_BYTES (2 * BUF_HALVES * 2)   /* 40960 */

__device__ __forceinline__ uint32_t smem_u32(const void* p) {
    uint32_t a;
    asm("{ .reg .u64 t; cvta.to.shared.u64 t, %1; cvt.u32.u64 %0, t; }"
        : "=r"(a) : "l"(p));
    return a;
}
__device__ __forceinline__ void cp16(uint32_t dst, const void* src) {
    asm volatile("cp.async.ca.shared.global [%0], [%1], 16;"
                 :: "r"(dst), "l"(src));
}
__device__ __forceinline__ void cp_commit() {
    asm volatile("cp.async.commit_group;" ::: "memory");
}
template <int N>
__device__ __forceinline__ void cp_wait() {
    asm volatile("cp.async.wait_group %0;" :: "n"(N) : "memory");
}
__device__ __forceinline__ void ldsm4(uint32_t& r0, uint32_t& r1,
                                      uint32_t& r2, uint32_t& r3, uint32_t addr) {
    asm volatile("ldmatrix.sync.aligned.m8n8.x4.shared.b16 {%0,%1,%2,%3}, [%4];"
                 : "=r"(r0), "=r"(r1), "=r"(r2), "=r"(r3) : "r"(addr));
}
__device__ __forceinline__ void mmah16(float* d, const uint32_t* a, const uint32_t* b) {
    asm volatile(
        "mma.sync.aligned.m16n8k16.row.col.f32.f16.f16.f32 "
        "{%0,%1,%2,%3}, {%4,%5,%6,%7}, {%8,%9}, {%0,%1,%2,%3};"
        : "+f"(d[0]), "+f"(d[1]), "+f"(d[2]), "+f"(d[3])
        : "r"(a[0]), "r"(a[1]), "r"(a[2]), "r"(a[3]), "r"(b[0]), "r"(b[1]));
}

__global__ __launch_bounds__(256, 2)
void gemm_kernel(const float* __restrict__ bias) {
    extern __shared__ __half sm[];
    const uint32_t sb = smem_u32(sm);
    const int tid  = threadIdx.x;
    const int lane = tid & 31;
    const int wid  = tid >> 5;
    const int wm   = (wid & 3) * 32;
    const int wn   = (wid >> 2) * 64;
    const int mBase = blockIdx.y * 128;
    const int nBase = blockIdx.x * 128;

    const int g = lane >> 3;
    const int i = lane & 7;
    const int a_row_off = (wm + i + ((g & 1) << 3)) * 40 + ((g >> 1) << 3);
    const int b_col_off = ((g & 1) << 3);
    const int b_row_i   = wn + ((g >> 1) << 3) + i;

    auto stage = [&](int buf, int kc) {
        uint32_t base = sb + buf * (BUF_HALVES * 2);
#pragma unroll
        for (int t4 = 0; t4 < 4; t4++) {
            int t = tid + t4 * 256;
            if (t < 512) {
                int r = t >> 2, c = t & 3;
                cp16(base + (OFF_AH + r * 40) * 2 + c * 16,
                     g_Ah + (size_t)(mBase + r) * DIM + kc * 32 + c * 8);
            } else {
                int idx = t - 512, r = idx >> 2, c = idx & 3;
                cp16(base + (OFF_BH + r * 40) * 2 + c * 16,
                     g_Wh + (size_t)(nBase + r) * DIM + kc * 32 + c * 8);
            }
        }
    };

    float acc[2][8][4];
#pragma unroll
    for (int x = 0; x < 2; x++)
#pragma unroll
        for (int j = 0; j < 8; j++)
#pragma unroll
            for (int k = 0; k < 4; k++) acc[x][j][k] = 0.f;

    stage(0, 0);
    cp_commit();

    int buf = 0;
    for (int kc = 0; kc < 8; kc++) {
        if (kc < 7) {
            stage(buf ^ 1, kc + 1);
            cp_commit();
            cp_wait<1>();
        } else {
            cp_wait<0>();
        }
        __syncthreads();

        const uint32_t base = sb + buf * (BUF_HALVES * 2);

#pragma unroll
        for (int kk = 0; kk < 32; kk += 16) {
            uint32_t ah[2][4];
#pragma unroll
            for (int mt = 0; mt < 2; mt++) {
                uint32_t addr = base + (OFF_AH + a_row_off + mt * 16 * 40 + kk) * 2;
                ldsm4(ah[mt][0], ah[mt][1], ah[mt][2], ah[mt][3], addr);
            }
            uint32_t bh[8][2];
#pragma unroll
            for (int p = 0; p < 4; p++) {
                uint32_t addr = base + (OFF_BH + (b_row_i + p * 16) * 40 + kk + b_col_off) * 2;
                ldsm4(bh[2 * p][0], bh[2 * p][1], bh[2 * p + 1][0], bh[2 * p + 1][1], addr);
            }
#pragma unroll
            for (int mt = 0; mt < 2; mt++)
#pragma unroll
                for (int nt = 0; nt < 8; nt++)
                    mmah16(acc[mt][nt], ah[mt], bh[nt]);
        }
        __syncthreads();
        buf ^= 1;
    }

#pragma unroll
    for (int mt = 0; mt < 2; mt++) {
#pragma unroll
        for (int nt = 0; nt < 8; nt++) {
            int row = mBase + wm + mt * 16 + (lane >> 2);
            int col = nBase + wn + nt * 8 + 2 * (lane & 3);
            float b0 = bias[col], b1 = bias[col + 1];
            if (row < N_NODES) {
                __half2 h = __floats2half2_rn(acc[mt][nt][0] + b0, acc[mt][nt][1] + b1);
                *reinterpret_cast<__half2*>(&g_proph[(size_t)row * NBIG + col]) = h;
            }
            if (row + 8 < N_NODES) {
                __half2 h = __floats2half2_rn(acc[mt][nt][2] + b0, acc[mt][nt][3] + b1);
                *reinterpret_cast<__half2*>(&g_proph[(size_t)(row + 8) * NBIG + col]) = h;
            }
        }
    }
}

// ---------------- message: padded segments, ping-pong pipeline --------------
__device__ __forceinline__ void acc_rec(uint4 v, uint4 g, float4& a0, float4& a1) {
    float2 f, gg;
    f  = __half22float2(*reinterpret_cast<__half2*>(&v.x));
    gg = __half22float2(*reinterpret_cast<__half2*>(&g.x));
    a0.x += f.x * gg.x; a0.y += f.y * gg.y;
    f  = __half22float2(*reinterpret_cast<__half2*>(&v.y));
    gg = __half22float2(*reinterpret_cast<__half2*>(&g.y));
    a0.z += f.x * gg.x; a0.w += f.y * gg.y;
    f  = __half22float2(*reinterpret_cast<__half2*>(&v.z));
    gg = __half22float2(*reinterpret_cast<__half2*>(&g.z));
    a1.x += f.x * gg.x; a1.y += f.y * gg.y;
    f  = __half22float2(*reinterpret_cast<__half2*>(&v.w));
    gg = __half22float2(*reinterpret_cast<__half2*>(&g.w));
    a1.z += f.x * gg.x; a1.w += f.y * gg.y;
}

#define LOAD4(E, V, G) do {                                                     \
    uint32_t _c0 = g_sorted[(E)];     uint32_t _c1 = g_sorted[(E) + 1];         \
    uint32_t _c2 = g_sorted[(E) + 2]; uint32_t _c3 = g_sorted[(E) + 3];         \
    V[0] = __ldg(reinterpret_cast<const uint4*>(                                \
        g_proph + (size_t)(_c0 >> 12) * NBIG + ((_c0 >> 9) & 7) * DIM) + lane); \
    V[1] = __ldg(reinterpret_cast<const uint4*>(                                \
        g_proph + (size_t)(_c1 >> 12) * NBIG + ((_c1 >> 9) & 7) * DIM) + lane); \
    V[2] = __ldg(reinterpret_cast<const uint4*>(                                \
        g_proph + (size_t)(_c2 >> 12) * NBIG + ((_c2 >> 9) & 7) * DIM) + lane); \
    V[3] = __ldg(reinterpret_cast<const uint4*>(                                \
        g_proph + (size_t)(_c3 >> 12) * NBIG + ((_c3 >> 9) & 7) * DIM) + lane); \
    G[0] = __ldg(reinterpret_cast<const uint4*>(                                \
        g_gatingh + (size_t)(_c0 & 511) * DIM) + lane);                         \
    G[1] = __ldg(reinterpret_cast<const uint4*>(                                \
        g_gatingh + (size_t)(_c1 & 511) * DIM) + lane);                         \
    G[2] = __ldg(reinterpret_cast<const uint4*>(                                \
        g_gatingh + (size_t)(_c2 & 511) * DIM) + lane);                         \
    G[3] = __ldg(reinterpret_cast<const uint4*>(                                \
        g_gatingh + (size_t)(_c3 & 511) * DIM) + lane);                         \
} while (0)

#define CONS4(V, G) do {                                                        \
    acc_rec(V[0], G[0], a0, a1);                                                \
    acc_rec(V[1], G[1], a0, a1);                                                \
    acc_rec(V[2], G[2], a0, a1);                                                \
    acc_rec(V[3], G[3], a0, a1);                                                \
} while (0)

__global__ __launch_bounds__(256)
void message_kernel(float* __restrict__ out) {
    int t    = (blockIdx.x * blockDim.x + threadIdx.x) >> 5;
    int lane = threadIdx.x & 31;
    if (t >= N_NODES) return;

    const int s0 = g_off[t];
    const int s1 = g_off[t + 1];    // padded end (multiple of 8 length)

    float4 a0 = make_float4(0.f, 0.f, 0.f, 0.f);
    float4 a1 = make_float4(0.f, 0.f, 0.f, 0.f);

    if (s0 < s1) {
        uint4 vA[4], gA[4], vB[4], gB[4];
        LOAD4(s0, vA, gA);
        int e = s0;
        for (; e + 8 < s1; e += 8) {
            LOAD4(e + 4, vB, gB);
            CONS4(vA, gA);
            LOAD4(e + 8, vA, gA);
            CONS4(vB, gB);
        }
        LOAD4(e + 4, vB, gB);
        CONS4(vA, gA);
        CONS4(vB, gB);
    }

    int deg = g_cnt[t];             // true degree
    float div = ((deg == 0) ? 1.0f : (float)deg) + 1e-8f;
    float s = 1.0f / div;
    a0.x *= s; a0.y *= s; a0.z *= s; a0.w *= s;
    a1.x *= s; a1.y *= s; a1.z *= s; a1.w *= s;

    float4* dst = reinterpret_cast<float4*>(out + (size_t)t * DIM) + lane * 2;
    dst[0] = a0;
    dst[1] = a1;
}

// ---------------- launch: two-stream fork/join (capture-legal) ---------------
extern "C" void kernel_launch(void* const* d_in, const int* in_sizes, int n_in,
                              void* d_out, int out_size) {
    const float* node_states = (const float*)d_in[0];
    const float* W    = (const float*)d_in[1];
    const float* b    = (const float*)d_in[2];
    const float* Wp   = (const float*)d_in[3];
    const float* bp   = (const float*)d_in[4];
    const int*   edges = (const int*)d_in[5];
    const int*   posl  = (const int*)d_in[6];
    float* out = (float*)d_out;

    static cudaStream_t sB = nullptr;
    static cudaEvent_t  evFork = nullptr, evJoin = nullptr;
    if (!sB) {
        cudaStreamCreateWithFlags(&sB, cudaStreamNonBlocking);
        cudaEventCreateWithFlags(&evFork, cudaEventDisableTiming);
        cudaEventCreateWithFlags(&evJoin, cudaEventDisableTiming);
        cudaFuncSetAttribute(gemm_kernel,
                             cudaFuncAttributeMaxDynamicSharedMemorySize,
                             SMEM_GEMM_BYTES);
    }

    cudaEventRecord(evFork, 0);
    cudaStreamWaitEvent(sB, evFork, 0);

    // chain B (stream sB): gating (+zero hist) -> hist -> scan -> place -> fill
    gating_kernel<<<POS_TAB, 256, 0, sB>>>(Wp, bp);
    hist_kernel<<<(TOTAL_EDGES + 255) / 256, 256, 0, sB>>>(edges);
    scan1_kernel<<<N_SBLK, SCAN_BLK, 0, sB>>>();
    scan2_kernel<<<1, 128, 0, sB>>>();
    scan3_kernel<<<N_SBLK, SCAN_BLK, 0, sB>>>();
    place_kernel<<<(TOTAL_EDGES + 255) / 256, 256, 0, sB>>>(edges, posl);
    fill_kernel<<<(N_NODES + 255) / 256, 256, 0, sB>>>();
    cudaEventRecord(evJoin, sB);

    // chain A (default stream): convert -> gemm
    convert_kernel<<<((N_NODES + NBIG) * DIM + 255) / 256, 256>>>(node_states, W);
    dim3 gg(NBIG / 128, N_PAD / 128);
    gemm_kernel<<<gg, 256, SMEM_GEMM_BYTES>>>(b);

    cudaStreamWaitEvent(0, evJoin, 0);
    message_kernel<<<(N_NODES * 32 + 255) / 256, 256>>>(out);
}